// round 1
// baseline (speedup 1.0000x reference)
#include <cuda_runtime.h>
#include <math.h>

#define BATCH 8
#define SEQ   2048
#define EMB   1024
#define DH    64
#define NROWS (BATCH * SEQ)   // 16384

// Scratch for projected Q, K, V: [B*S][64] each (4 MB each). __device__ globals
// (no allocation allowed in kernel_launch).
__device__ float g_Q[NROWS * DH];
__device__ float g_K[NROWS * DH];
__device__ float g_V[NROWS * DH];

// ---------------------------------------------------------------------------
// Kernel 1: QKV projection.  out = x @ W + b, split into Q/K/V scratch.
// x: [16384, 1024], W: [1024, 192], b: [192].
// BM=128, BN=64 (exactly one of Q/K/V per y-block), BK=16, 256 threads,
// per-thread 8x4 micro-tile.
// ---------------------------------------------------------------------------
__global__ __launch_bounds__(256) void qkv_kernel(
    const float* __restrict__ x,
    const float* __restrict__ W,
    const float* __restrict__ bias)
{
    __shared__ float As[16][132];  // [k][m], padded
    __shared__ float Bs[16][68];   // [k][n], padded

    const int nblk = blockIdx.y;        // 0=Q, 1=K, 2=V
    const int m0   = blockIdx.x * 128;
    const int tid  = threadIdx.x;
    const int ty   = tid >> 4;          // 0..15 -> m rows 8*ty..
    const int tx   = tid & 15;          // 0..15 -> n cols 4*tx..

    const float* xblk = x + (size_t)m0 * EMB;
    const float* Wcol = W + nblk * 64;

    float acc[8][4];
    #pragma unroll
    for (int i = 0; i < 8; i++)
        #pragma unroll
        for (int j = 0; j < 4; j++) acc[i][j] = 0.0f;

    for (int k0 = 0; k0 < EMB; k0 += 16) {
        __syncthreads();
        // Load x tile 128x16 -> As[k][m] (transposed). 512 float4 units, 2/thread.
        #pragma unroll
        for (int u = 0; u < 2; u++) {
            int id  = tid + u * 256;         // 0..511
            int row = id >> 2;               // 0..127
            int c4  = id & 3;                // 0..3
            float4 v = *(const float4*)&xblk[(size_t)row * EMB + k0 + c4 * 4];
            As[c4 * 4 + 0][row] = v.x;
            As[c4 * 4 + 1][row] = v.y;
            As[c4 * 4 + 2][row] = v.z;
            As[c4 * 4 + 3][row] = v.w;
        }
        // Load W tile 16x64 -> Bs[k][n]. 256 float4 units, 1/thread.
        {
            int r  = tid >> 4;   // k row 0..15
            int c4 = tid & 15;   // 0..15
            float4 v = *(const float4*)&Wcol[(size_t)(k0 + r) * 192 + c4 * 4];
            *(float4*)&Bs[r][c4 * 4] = v;
        }
        __syncthreads();

        #pragma unroll
        for (int k = 0; k < 16; k++) {
            float4 a0 = *(float4*)&As[k][ty * 8];
            float4 a1 = *(float4*)&As[k][ty * 8 + 4];
            float4 b  = *(float4*)&Bs[k][tx * 4];
            float af[8] = {a0.x, a0.y, a0.z, a0.w, a1.x, a1.y, a1.z, a1.w};
            float bf[4] = {b.x, b.y, b.z, b.w};
            #pragma unroll
            for (int i = 0; i < 8; i++)
                #pragma unroll
                for (int j = 0; j < 4; j++)
                    acc[i][j] = fmaf(af[i], bf[j], acc[i][j]);
        }
    }

    float* dst = (nblk == 0) ? g_Q : (nblk == 1) ? g_K : g_V;
    float bb[4];
    #pragma unroll
    for (int j = 0; j < 4; j++) bb[j] = bias[nblk * 64 + tx * 4 + j];

    #pragma unroll
    for (int i = 0; i < 8; i++) {
        float4 o;
        o.x = acc[i][0] + bb[0];
        o.y = acc[i][1] + bb[1];
        o.z = acc[i][2] + bb[2];
        o.w = acc[i][3] + bb[3];
        *(float4*)&dst[(size_t)(m0 + ty * 8 + i) * DH + tx * 4] = o;
    }
}

// ---------------------------------------------------------------------------
// Kernel 2: fused masked attention, flash-style online softmax.
// One block = (batch b, 64 query rows). 256 threads, 4x4 micro-tiles.
// NOTE semantics: masked scores are set to 0.0 and PARTICIPATE in softmax.
// ---------------------------------------------------------------------------
__global__ __launch_bounds__(256) void attn_kernel(
    const int* __restrict__ mask,
    float* __restrict__ out)
{
    extern __shared__ float sm[];
    float* qT = sm;                 // [d][q]  64x68
    float* kT = sm + 64 * 68;       // [d][k]  64x68
    float* pT = sm + 2 * 64 * 68;   // [k][q]  64x68
    float* vS = sm + 3 * 64 * 68;   // [k][d]  64x68

    const int b  = blockIdx.y;
    const int q0 = blockIdx.x * 64;
    const int tid = threadIdx.x;
    const int ty = tid >> 4;   // 0..15 -> q rows 4*ty..
    const int tx = tid & 15;   // 0..15 -> k (gemm1) / d (gemm2) cols 4*tx..

    const float* Qb = g_Q + ((size_t)b * SEQ + q0) * DH;
    const float* Kb = g_K + (size_t)b * SEQ * DH;
    const float* Vb = g_V + (size_t)b * SEQ * DH;
    const int*   mb = mask + ((size_t)b * SEQ + q0) * SEQ;

    // Load Q tile (64x64) transposed into qT[d][q]. 1024 float4 units, 4/thread.
    #pragma unroll
    for (int u = 0; u < 4; u++) {
        int id  = tid + u * 256;
        int row = id >> 4;       // q row 0..63
        int c4  = id & 15;       // d group
        float4 v = *(const float4*)&Qb[(size_t)row * DH + c4 * 4];
        qT[(c4 * 4 + 0) * 68 + row] = v.x;
        qT[(c4 * 4 + 1) * 68 + row] = v.y;
        qT[(c4 * 4 + 2) * 68 + row] = v.z;
        qT[(c4 * 4 + 3) * 68 + row] = v.w;
    }

    float m_i[4], l_i[4], acc[4][4];
    #pragma unroll
    for (int i = 0; i < 4; i++) {
        m_i[i] = -INFINITY;
        l_i[i] = 0.0f;
        #pragma unroll
        for (int j = 0; j < 4; j++) acc[i][j] = 0.0f;
    }

    const float scale = 0.125f;  // 1/sqrt(64)

    for (int kt = 0; kt < SEQ / 64; kt++) {
        __syncthreads();  // previous iteration done reading kT/vS/pT
        const float* Kt = Kb + (size_t)kt * 64 * DH;
        const float* Vt = Vb + (size_t)kt * 64 * DH;
        #pragma unroll
        for (int u = 0; u < 4; u++) {
            int id  = tid + u * 256;
            int row = id >> 4;
            int c4  = id & 15;
            float4 kv = *(const float4*)&Kt[(size_t)row * DH + c4 * 4];
            kT[(c4 * 4 + 0) * 68 + row] = kv.x;
            kT[(c4 * 4 + 1) * 68 + row] = kv.y;
            kT[(c4 * 4 + 2) * 68 + row] = kv.z;
            kT[(c4 * 4 + 3) * 68 + row] = kv.w;
            float4 vv = *(const float4*)&Vt[(size_t)row * DH + c4 * 4];
            *(float4*)&vS[row * 68 + c4 * 4] = vv;
        }
        // Mask values for this thread's 4x4 score tile (coalesced int4 per row).
        int4 mr[4];
        #pragma unroll
        for (int i = 0; i < 4; i++)
            mr[i] = *(const int4*)&mb[(size_t)(4 * ty + i) * SEQ + kt * 64 + tx * 4];
        __syncthreads();  // tiles ready

        // GEMM1: S = Q @ K^T  (4x4 per thread)
        float s[4][4];
        #pragma unroll
        for (int i = 0; i < 4; i++)
            #pragma unroll
            for (int j = 0; j < 4; j++) s[i][j] = 0.0f;

        #pragma unroll 8
        for (int d = 0; d < 64; d++) {
            float4 a = *(float4*)&qT[d * 68 + 4 * ty];
            float4 bq = *(float4*)&kT[d * 68 + 4 * tx];
            float af[4] = {a.x, a.y, a.z, a.w};
            float bf[4] = {bq.x, bq.y, bq.z, bq.w};
            #pragma unroll
            for (int i = 0; i < 4; i++)
                #pragma unroll
                for (int j = 0; j < 4; j++)
                    s[i][j] = fmaf(af[i], bf[j], s[i][j]);
        }

        // Apply mask (mask==1 -> score 0.0, still in softmax) and scale.
        #pragma unroll
        for (int i = 0; i < 4; i++) {
            int mm[4] = {mr[i].x, mr[i].y, mr[i].z, mr[i].w};
            #pragma unroll
            for (int j = 0; j < 4; j++)
                s[i][j] = (mm[j] == 1) ? 0.0f : s[i][j] * scale;
        }

        // Online softmax per query row (row spread across 16 lanes via tx).
        #pragma unroll
        for (int i = 0; i < 4; i++) {
            float rmax = fmaxf(fmaxf(s[i][0], s[i][1]), fmaxf(s[i][2], s[i][3]));
            #pragma unroll
            for (int off = 1; off < 16; off <<= 1)
                rmax = fmaxf(rmax, __shfl_xor_sync(0xffffffffu, rmax, off));
            float m_new = fmaxf(m_i[i], rmax);
            float f = __expf(m_i[i] - m_new);
            m_i[i] = m_new;
            float rsum = 0.0f;
            #pragma unroll
            for (int j = 0; j < 4; j++) {
                float p = __expf(s[i][j] - m_new);
                s[i][j] = p;
                rsum += p;
            }
            #pragma unroll
            for (int off = 1; off < 16; off <<= 1)
                rsum += __shfl_xor_sync(0xffffffffu, rsum, off);
            l_i[i] = l_i[i] * f + rsum;
            #pragma unroll
            for (int j = 0; j < 4; j++) acc[i][j] *= f;
        }

        // Write P transposed: pT[k_local][q_local]
        #pragma unroll
        for (int j = 0; j < 4; j++)
            #pragma unroll
            for (int i = 0; i < 4; i++)
                pT[(4 * tx + j) * 68 + (4 * ty + i)] = s[i][j];
        __syncthreads();  // pT ready

        // GEMM2: acc += P @ V  (4x4 per thread; j now indexes d cols)
        #pragma unroll 8
        for (int kk = 0; kk < 64; kk++) {
            float4 a = *(float4*)&pT[kk * 68 + 4 * ty];
            float4 bv = *(float4*)&vS[kk * 68 + 4 * tx];
            float af[4] = {a.x, a.y, a.z, a.w};
            float bf[4] = {bv.x, bv.y, bv.z, bv.w};
            #pragma unroll
            for (int i = 0; i < 4; i++)
                #pragma unroll
                for (int j = 0; j < 4; j++)
                    acc[i][j] = fmaf(af[i], bf[j], acc[i][j]);
        }
    }

    // Epilogue: out[b][q][d] = acc / l
    #pragma unroll
    for (int i = 0; i < 4; i++) {
        float inv = 1.0f / l_i[i];
        float4 o;
        o.x = acc[i][0] * inv;
        o.y = acc[i][1] * inv;
        o.z = acc[i][2] * inv;
        o.w = acc[i][3] * inv;
        *(float4*)&out[((size_t)b * SEQ + q0 + 4 * ty + i) * DH + 4 * tx] = o;
    }
}

// ---------------------------------------------------------------------------
extern "C" void kernel_launch(void* const* d_in, const int* in_sizes, int n_in,
                              void* d_out, int out_size)
{
    const float* x    = (const float*)d_in[0];
    const int*   mask = (const int*)d_in[1];
    const float* W    = (const float*)d_in[2];
    const float* bias = (const float*)d_in[3];
    float* out = (float*)d_out;

    (void)in_sizes; (void)n_in; (void)out_size;

    // QKV projection: grid (16384/128, 3)
    dim3 g1(NROWS / 128, 3);
    qkv_kernel<<<g1, 256>>>(x, W, bias);

    // Attention: grid (2048/64 q-tiles, 8 batches), dynamic smem 4*64*68*4 B
    static int smem_set = 0;
    const int smem_bytes = 4 * 64 * 68 * sizeof(float);
    if (!smem_set) {
        cudaFuncSetAttribute(attn_kernel,
                             cudaFuncAttributeMaxDynamicSharedMemorySize,
                             smem_bytes);
        smem_set = 1;
    }
    dim3 g2(SEQ / 64, BATCH);
    attn_kernel<<<g2, 256, smem_bytes>>>(mask, out);
}

// round 3
// speedup vs baseline: 1.2064x; 1.2064x over previous
#include <cuda_runtime.h>
#include <cuda_bf16.h>
#include <math.h>
#include <stdint.h>

#define BATCH 8
#define SEQ   2048
#define EMB   1024
#define DH    64
#define NROWS (BATCH * SEQ)   // 16384

// Scratch: projected Q/K/V (fp32) and transposed hi/lo bf16 weights.
__device__ float g_Q[NROWS * DH];
__device__ float g_K[NROWS * DH];
__device__ float g_V[NROWS * DH];
__device__ __nv_bfloat16 g_WhiT[192 * EMB];  // [n][k] K-major
__device__ __nv_bfloat16 g_WloT[192 * EMB];

// ---------------------------------------------------------------------------
// mma.sync bf16 m16n8k16 helper (f32 accum, in-place)
// ---------------------------------------------------------------------------
__device__ __forceinline__ void mma_bf16(float* c, const uint32_t* a, const uint32_t* b) {
    asm volatile(
        "mma.sync.aligned.m16n8k16.row.col.f32.bf16.bf16.f32 "
        "{%0,%1,%2,%3}, {%4,%5,%6,%7}, {%8,%9}, {%0,%1,%2,%3};"
        : "+f"(c[0]), "+f"(c[1]), "+f"(c[2]), "+f"(c[3])
        : "r"(a[0]), "r"(a[1]), "r"(a[2]), "r"(a[3]), "r"(b[0]), "r"(b[1]));
}

// ---------------------------------------------------------------------------
// Kernel 0: convert W [1024,192] fp32 -> transposed hi/lo bf16 [192][1024]
// ---------------------------------------------------------------------------
__global__ void wconv_kernel(const float* __restrict__ W) {
    int idx = blockIdx.x * 256 + threadIdx.x;     // 0..196607
    int k = idx & 1023;
    int n = idx >> 10;                            // 0..191
    float w = W[(size_t)k * 192 + n];
    __nv_bfloat16 hi = __float2bfloat16(w);
    float lo = w - __bfloat162float(hi);
    g_WhiT[(size_t)n * EMB + k] = hi;
    g_WloT[(size_t)n * EMB + k] = __float2bfloat16(lo);
}

// ---------------------------------------------------------------------------
// Kernel 1: QKV projection via mma.sync bf16x3 split.
// BM=64 (rows), BN=192 (all of Q|K|V), BK=32. 256 threads = 8 warps,
// warp grid 4(M) x 2(N); each warp: 16 rows x 96 cols = 12 n8-tiles.
// smem tiles padded to stride 40 elements for conflict-free fragment loads.
// ---------------------------------------------------------------------------
#define ASTR 40
__global__ __launch_bounds__(256) void qkv_mma_kernel(
    const float* __restrict__ x,
    const float* __restrict__ bias)
{
    __shared__ __nv_bfloat16 sAhi[64 * ASTR];
    __shared__ __nv_bfloat16 sAlo[64 * ASTR];
    __shared__ __nv_bfloat16 sBhi[192 * ASTR];
    __shared__ __nv_bfloat16 sBlo[192 * ASTR];

    const int tid = threadIdx.x;
    const int wid = tid >> 5;
    const int lid = tid & 31;
    const int g   = lid >> 2;      // 0..7
    const int tig = lid & 3;       // 0..3
    const int warp_m = wid & 3;    // 0..3
    const int warp_n = wid >> 2;   // 0..1
    const int m0 = blockIdx.x * 64;

    float acc[12][4];
    #pragma unroll
    for (int j = 0; j < 12; j++)
        #pragma unroll
        for (int i = 0; i < 4; i++) acc[j][i] = 0.0f;

    for (int k0 = 0; k0 < EMB; k0 += 32) {
        __syncthreads();
        // --- stage A: x[m0..m0+63][k0..k0+31] fp32 -> hi/lo bf16, 512 float4, 2/thr
        #pragma unroll
        for (int u = 0; u < 2; u++) {
            int id  = tid + u * 256;
            int row = id >> 3;      // 0..63
            int c4  = id & 7;       // k-group of 4
            float4 v = *(const float4*)&x[(size_t)(m0 + row) * EMB + k0 + c4 * 4];
            __nv_bfloat16 h0 = __float2bfloat16(v.x);
            __nv_bfloat16 h1 = __float2bfloat16(v.y);
            __nv_bfloat16 h2 = __float2bfloat16(v.z);
            __nv_bfloat16 h3 = __float2bfloat16(v.w);
            __nv_bfloat162 hp0 = __halves2bfloat162(h0, h1);
            __nv_bfloat162 hp1 = __halves2bfloat162(h2, h3);
            __nv_bfloat162 lp0 = __halves2bfloat162(
                __float2bfloat16(v.x - __bfloat162float(h0)),
                __float2bfloat16(v.y - __bfloat162float(h1)));
            __nv_bfloat162 lp1 = __halves2bfloat162(
                __float2bfloat16(v.z - __bfloat162float(h2)),
                __float2bfloat16(v.w - __bfloat162float(h3)));
            int e = row * ASTR + c4 * 4;
            *(__nv_bfloat162*)&sAhi[e]     = hp0;
            *(__nv_bfloat162*)&sAhi[e + 2] = hp1;
            *(__nv_bfloat162*)&sAlo[e]     = lp0;
            *(__nv_bfloat162*)&sAlo[e + 2] = lp1;
        }
        // --- stage B: WT[n][k0..k0+31] hi/lo, 192 rows x 8 uint2 units = 1536, 6/thr
        #pragma unroll
        for (int u = 0; u < 6; u++) {
            int id  = tid + u * 256;
            int row = id >> 3;      // 0..191
            int c   = id & 7;       // group of 4 bf16
            uint2 vh = *(const uint2*)&g_WhiT[(size_t)row * EMB + k0 + c * 4];
            uint2 vl = *(const uint2*)&g_WloT[(size_t)row * EMB + k0 + c * 4];
            int e = row * ASTR + c * 4;
            *(uint2*)&sBhi[e] = vh;
            *(uint2*)&sBlo[e] = vl;
        }
        __syncthreads();

        // --- 2 k-steps of 16
        #pragma unroll
        for (int ks = 0; ks < 2; ks++) {
            const int kb = ks * 16;
            const int ra = warp_m * 16 + g;
            uint32_t ah[4], al[4];
            ah[0] = *(const uint32_t*)&sAhi[ra * ASTR + kb + 2 * tig];
            ah[1] = *(const uint32_t*)&sAhi[(ra + 8) * ASTR + kb + 2 * tig];
            ah[2] = *(const uint32_t*)&sAhi[ra * ASTR + kb + 8 + 2 * tig];
            ah[3] = *(const uint32_t*)&sAhi[(ra + 8) * ASTR + kb + 8 + 2 * tig];
            al[0] = *(const uint32_t*)&sAlo[ra * ASTR + kb + 2 * tig];
            al[1] = *(const uint32_t*)&sAlo[(ra + 8) * ASTR + kb + 2 * tig];
            al[2] = *(const uint32_t*)&sAlo[ra * ASTR + kb + 8 + 2 * tig];
            al[3] = *(const uint32_t*)&sAlo[(ra + 8) * ASTR + kb + 8 + 2 * tig];

            #pragma unroll
            for (int j = 0; j < 12; j++) {
                const int nb = warp_n * 96 + j * 8 + g;   // B row (n index)
                uint32_t bh[2], bl[2];
                bh[0] = *(const uint32_t*)&sBhi[nb * ASTR + kb + 2 * tig];
                bh[1] = *(const uint32_t*)&sBhi[nb * ASTR + kb + 8 + 2 * tig];
                bl[0] = *(const uint32_t*)&sBlo[nb * ASTR + kb + 2 * tig];
                bl[1] = *(const uint32_t*)&sBlo[nb * ASTR + kb + 8 + 2 * tig];
                mma_bf16(acc[j], ah, bh);
                mma_bf16(acc[j], ah, bl);
                mma_bf16(acc[j], al, bh);
            }
        }
    }

    // --- epilogue: add bias, scatter to g_Q / g_K / g_V
    const int row0 = m0 + warp_m * 16 + g;
    #pragma unroll
    for (int j = 0; j < 12; j++) {
        int nglob = warp_n * 96 + j * 8 + 2 * tig;   // stays within one 64-block
        float* dst = (nglob < 64) ? g_Q : (nglob < 128) ? g_K : g_V;
        int col = nglob & 63;
        float b0 = bias[nglob], b1 = bias[nglob + 1];
        float2 o0 = make_float2(acc[j][0] + b0, acc[j][1] + b1);
        float2 o1 = make_float2(acc[j][2] + b0, acc[j][3] + b1);
        *(float2*)&dst[(size_t)row0 * DH + col]       = o0;
        *(float2*)&dst[(size_t)(row0 + 8) * DH + col] = o1;
    }
}

// ---------------------------------------------------------------------------
// Kernel 2: fused masked attention (R1 passing version, unchanged).
// ---------------------------------------------------------------------------
__global__ __launch_bounds__(256) void attn_kernel(
    const int* __restrict__ mask,
    float* __restrict__ out)
{
    extern __shared__ float sm[];
    float* qT = sm;                 // [d][q]  64x68
    float* kT = sm + 64 * 68;       // [d][k]  64x68
    float* pT = sm + 2 * 64 * 68;   // [k][q]  64x68
    float* vS = sm + 3 * 64 * 68;   // [k][d]  64x68

    const int b  = blockIdx.y;
    const int q0 = blockIdx.x * 64;
    const int tid = threadIdx.x;
    const int ty = tid >> 4;
    const int tx = tid & 15;

    const float* Qb = g_Q + ((size_t)b * SEQ + q0) * DH;
    const float* Kb = g_K + (size_t)b * SEQ * DH;
    const float* Vb = g_V + (size_t)b * SEQ * DH;
    const int*   mb = mask + ((size_t)b * SEQ + q0) * SEQ;

    #pragma unroll
    for (int u = 0; u < 4; u++) {
        int id  = tid + u * 256;
        int row = id >> 4;
        int c4  = id & 15;
        float4 v = *(const float4*)&Qb[(size_t)row * DH + c4 * 4];
        qT[(c4 * 4 + 0) * 68 + row] = v.x;
        qT[(c4 * 4 + 1) * 68 + row] = v.y;
        qT[(c4 * 4 + 2) * 68 + row] = v.z;
        qT[(c4 * 4 + 3) * 68 + row] = v.w;
    }

    float m_i[4], l_i[4], acc[4][4];
    #pragma unroll
    for (int i = 0; i < 4; i++) {
        m_i[i] = -INFINITY;
        l_i[i] = 0.0f;
        #pragma unroll
        for (int j = 0; j < 4; j++) acc[i][j] = 0.0f;
    }

    const float scale = 0.125f;

    for (int kt = 0; kt < SEQ / 64; kt++) {
        __syncthreads();
        const float* Kt = Kb + (size_t)kt * 64 * DH;
        const float* Vt = Vb + (size_t)kt * 64 * DH;
        #pragma unroll
        for (int u = 0; u < 4; u++) {
            int id  = tid + u * 256;
            int row = id >> 4;
            int c4  = id & 15;
            float4 kv = *(const float4*)&Kt[(size_t)row * DH + c4 * 4];
            kT[(c4 * 4 + 0) * 68 + row] = kv.x;
            kT[(c4 * 4 + 1) * 68 + row] = kv.y;
            kT[(c4 * 4 + 2) * 68 + row] = kv.z;
            kT[(c4 * 4 + 3) * 68 + row] = kv.w;
            float4 vv = *(const float4*)&Vt[(size_t)row * DH + c4 * 4];
            *(float4*)&vS[row * 68 + c4 * 4] = vv;
        }
        int4 mr[4];
        #pragma unroll
        for (int i = 0; i < 4; i++)
            mr[i] = *(const int4*)&mb[(size_t)(4 * ty + i) * SEQ + kt * 64 + tx * 4];
        __syncthreads();

        float s[4][4];
        #pragma unroll
        for (int i = 0; i < 4; i++)
            #pragma unroll
            for (int j = 0; j < 4; j++) s[i][j] = 0.0f;

        #pragma unroll 8
        for (int d = 0; d < 64; d++) {
            float4 a = *(float4*)&qT[d * 68 + 4 * ty];
            float4 bq = *(float4*)&kT[d * 68 + 4 * tx];
            float af[4] = {a.x, a.y, a.z, a.w};
            float bf[4] = {bq.x, bq.y, bq.z, bq.w};
            #pragma unroll
            for (int i = 0; i < 4; i++)
                #pragma unroll
                for (int j = 0; j < 4; j++)
                    s[i][j] = fmaf(af[i], bf[j], s[i][j]);
        }

        #pragma unroll
        for (int i = 0; i < 4; i++) {
            int mm[4] = {mr[i].x, mr[i].y, mr[i].z, mr[i].w};
            #pragma unroll
            for (int j = 0; j < 4; j++)
                s[i][j] = (mm[j] == 1) ? 0.0f : s[i][j] * scale;
        }

        #pragma unroll
        for (int i = 0; i < 4; i++) {
            float rmax = fmaxf(fmaxf(s[i][0], s[i][1]), fmaxf(s[i][2], s[i][3]));
            #pragma unroll
            for (int off = 1; off < 16; off <<= 1)
                rmax = fmaxf(rmax, __shfl_xor_sync(0xffffffffu, rmax, off));
            float m_new = fmaxf(m_i[i], rmax);
            float f = __expf(m_i[i] - m_new);
            m_i[i] = m_new;
            float rsum = 0.0f;
            #pragma unroll
            for (int j = 0; j < 4; j++) {
                float p = __expf(s[i][j] - m_new);
                s[i][j] = p;
                rsum += p;
            }
            #pragma unroll
            for (int off = 1; off < 16; off <<= 1)
                rsum += __shfl_xor_sync(0xffffffffu, rsum, off);
            l_i[i] = l_i[i] * f + rsum;
            #pragma unroll
            for (int j = 0; j < 4; j++) acc[i][j] *= f;
        }

        #pragma unroll
        for (int j = 0; j < 4; j++)
            #pragma unroll
            for (int i = 0; i < 4; i++)
                pT[(4 * tx + j) * 68 + (4 * ty + i)] = s[i][j];
        __syncthreads();

        #pragma unroll 8
        for (int kk = 0; kk < 64; kk++) {
            float4 a = *(float4*)&pT[kk * 68 + 4 * ty];
            float4 bv = *(float4*)&vS[kk * 68 + 4 * tx];
            float af[4] = {a.x, a.y, a.z, a.w};
            float bf[4] = {bv.x, bv.y, bv.z, bv.w};
            #pragma unroll
            for (int i = 0; i < 4; i++)
                #pragma unroll
                for (int j = 0; j < 4; j++)
                    acc[i][j] = fmaf(af[i], bf[j], acc[i][j]);
        }
    }

    #pragma unroll
    for (int i = 0; i < 4; i++) {
        float inv = 1.0f / l_i[i];
        float4 o;
        o.x = acc[i][0] * inv;
        o.y = acc[i][1] * inv;
        o.z = acc[i][2] * inv;
        o.w = acc[i][3] * inv;
        *(float4*)&out[((size_t)b * SEQ + q0 + 4 * ty + i) * DH + 4 * tx] = o;
    }
}

// ---------------------------------------------------------------------------
extern "C" void kernel_launch(void* const* d_in, const int* in_sizes, int n_in,
                              void* d_out, int out_size)
{
    const float* x    = (const float*)d_in[0];
    const int*   mask = (const int*)d_in[1];
    const float* W    = (const float*)d_in[2];
    const float* bias = (const float*)d_in[3];
    float* out = (float*)d_out;

    (void)in_sizes; (void)n_in; (void)out_size;

    static int attr_set = 0;
    const int attn_smem = 4 * 64 * 68 * sizeof(float);
    if (!attr_set) {
        cudaFuncSetAttribute(attn_kernel,
                             cudaFuncAttributeMaxDynamicSharedMemorySize, attn_smem);
        attr_set = 1;
    }

    // W -> bf16 hi/lo transposed
    wconv_kernel<<<(192 * EMB) / 256, 256>>>(W);

    // QKV projection on tensor cores (mma.sync bf16x3)
    qkv_mma_kernel<<<NROWS / 64, 256>>>(x, bias);

    // Attention
    dim3 g2(SEQ / 64, BATCH);
    attn_kernel<<<g2, 256, attn_smem>>>(mask, out);
}

// round 4
// speedup vs baseline: 1.8618x; 1.5432x over previous
#include <cuda_runtime.h>
#include <cuda_bf16.h>
#include <math.h>
#include <stdint.h>

#define BATCH 8
#define SEQ   2048
#define EMB   1024
#define DH    64
#define NROWS (BATCH * SEQ)   // 16384

// Pre-split bf16 operands produced by the QKV kernel.
__device__ __nv_bfloat16 g_Qhi[NROWS * DH];
__device__ __nv_bfloat16 g_Qlo[NROWS * DH];
__device__ __nv_bfloat16 g_Khi[NROWS * DH];
__device__ __nv_bfloat16 g_Klo[NROWS * DH];
__device__ __nv_bfloat16 g_VThi[BATCH * DH * SEQ];  // [b][d][s]
__device__ __nv_bfloat16 g_VTlo[BATCH * DH * SEQ];
__device__ __nv_bfloat16 g_WhiT[192 * EMB];          // [n][k]
__device__ __nv_bfloat16 g_WloT[192 * EMB];

// ---------------------------------------------------------------------------
// helpers
// ---------------------------------------------------------------------------
__device__ __forceinline__ void mma_bf16(float* c, const uint32_t* a, const uint32_t* b) {
    asm volatile(
        "mma.sync.aligned.m16n8k16.row.col.f32.bf16.bf16.f32 "
        "{%0,%1,%2,%3}, {%4,%5,%6,%7}, {%8,%9}, {%0,%1,%2,%3};"
        : "+f"(c[0]), "+f"(c[1]), "+f"(c[2]), "+f"(c[3])
        : "r"(a[0]), "r"(a[1]), "r"(a[2]), "r"(a[3]), "r"(b[0]), "r"(b[1]));
}

__device__ __forceinline__ uint32_t smem_u32(const void* p) {
    uint32_t a;
    asm("{ .reg .u64 t; cvta.to.shared.u64 t, %1; cvt.u32.u64 %0, t; }"
        : "=r"(a) : "l"(p));
    return a;
}

__device__ __forceinline__ void cp16(uint32_t dst, const void* src) {
    asm volatile("cp.async.cg.shared.global [%0], [%1], 16;" :: "r"(dst), "l"(src));
}
#define CP_COMMIT() asm volatile("cp.async.commit_group;" ::: "memory")

// Fast 2^t on the FMA pipe (abs err ~2.4e-6 for |t| <= ~12).
__device__ __forceinline__ float fexp2(float t) {
    float z = t + 12582912.0f;                 // round to nearest int
    float f = t - (z - 12582912.0f);           // f in [-0.5, 0.5]
    int   e = __float_as_int(z) << 23;         // n << 23
    float p = 0.0013333558f;
    p = fmaf(p, f, 0.0096181291f);
    p = fmaf(p, f, 0.0555041087f);
    p = fmaf(p, f, 0.2402265070f);
    p = fmaf(p, f, 0.6931471806f);
    p = fmaf(p, f, 1.0f);
    return __int_as_float(__float_as_int(p) + e);
}

__device__ __forceinline__ uint32_t pack_hi(float a, float b) {
    __nv_bfloat162 h = __halves2bfloat162(__float2bfloat16(a), __float2bfloat16(b));
    return *(uint32_t*)&h;
}
__device__ __forceinline__ uint32_t pack_lo(float a, float b) {
    __nv_bfloat16 ha = __float2bfloat16(a), hb = __float2bfloat16(b);
    __nv_bfloat162 l = __halves2bfloat162(
        __float2bfloat16(a - __bfloat162float(ha)),
        __float2bfloat16(b - __bfloat162float(hb)));
    return *(uint32_t*)&l;
}

// ---------------------------------------------------------------------------
// Kernel 0: W [1024,192] fp32 -> transposed hi/lo bf16 [192][1024]
// ---------------------------------------------------------------------------
__global__ void wconv_kernel(const float* __restrict__ W) {
    int idx = blockIdx.x * 256 + threadIdx.x;
    int k = idx & 1023;
    int n = idx >> 10;
    float w = W[(size_t)k * 192 + n];
    __nv_bfloat16 hi = __float2bfloat16(w);
    g_WhiT[(size_t)n * EMB + k] = hi;
    g_WloT[(size_t)n * EMB + k] = __float2bfloat16(w - __bfloat162float(hi));
}

// ---------------------------------------------------------------------------
// Kernel 1: QKV projection (mma.sync bf16x3). Emits pre-split bf16 hi/lo
// Q, K (row-major) and transposed VT (via smem staging).
// ---------------------------------------------------------------------------
#define ASTR 40
#define QSM_AHI 0
#define QSM_ALO 5120
#define QSM_BHI 10240
#define QSM_BLO 25600
#define QSM_TOT 40960

__global__ __launch_bounds__(256) void qkv_mma_kernel(
    const float* __restrict__ x,
    const float* __restrict__ bias)
{
    __shared__ char qsm[QSM_TOT];
    __nv_bfloat16* sAhi = (__nv_bfloat16*)(qsm + QSM_AHI);
    __nv_bfloat16* sAlo = (__nv_bfloat16*)(qsm + QSM_ALO);
    __nv_bfloat16* sBhi = (__nv_bfloat16*)(qsm + QSM_BHI);
    __nv_bfloat16* sBlo = (__nv_bfloat16*)(qsm + QSM_BLO);

    const int tid = threadIdx.x;
    const int wid = tid >> 5;
    const int lid = tid & 31;
    const int g   = lid >> 2;
    const int tig = lid & 3;
    const int warp_m = wid & 3;
    const int warp_n = wid >> 2;
    const int m0 = blockIdx.x * 64;

    float acc[12][4];
    #pragma unroll
    for (int j = 0; j < 12; j++)
        #pragma unroll
        for (int i = 0; i < 4; i++) acc[j][i] = 0.0f;

    for (int k0 = 0; k0 < EMB; k0 += 32) {
        __syncthreads();
        #pragma unroll
        for (int u = 0; u < 2; u++) {
            int id  = tid + u * 256;
            int row = id >> 3;
            int c4  = id & 7;
            float4 v = *(const float4*)&x[(size_t)(m0 + row) * EMB + k0 + c4 * 4];
            int e = row * ASTR + c4 * 4;
            *(uint32_t*)&sAhi[e]     = pack_hi(v.x, v.y);
            *(uint32_t*)&sAhi[e + 2] = pack_hi(v.z, v.w);
            *(uint32_t*)&sAlo[e]     = pack_lo(v.x, v.y);
            *(uint32_t*)&sAlo[e + 2] = pack_lo(v.z, v.w);
        }
        #pragma unroll
        for (int u = 0; u < 6; u++) {
            int id  = tid + u * 256;
            int row = id >> 3;
            int c   = id & 7;
            uint2 vh = *(const uint2*)&g_WhiT[(size_t)row * EMB + k0 + c * 4];
            uint2 vl = *(const uint2*)&g_WloT[(size_t)row * EMB + k0 + c * 4];
            int e = row * ASTR + c * 4;
            *(uint2*)&sBhi[e] = vh;
            *(uint2*)&sBlo[e] = vl;
        }
        __syncthreads();

        #pragma unroll
        for (int ks = 0; ks < 2; ks++) {
            const int kb = ks * 16;
            const int ra = warp_m * 16 + g;
            uint32_t ah[4], al[4];
            ah[0] = *(const uint32_t*)&sAhi[ra * ASTR + kb + 2 * tig];
            ah[1] = *(const uint32_t*)&sAhi[(ra + 8) * ASTR + kb + 2 * tig];
            ah[2] = *(const uint32_t*)&sAhi[ra * ASTR + kb + 8 + 2 * tig];
            ah[3] = *(const uint32_t*)&sAhi[(ra + 8) * ASTR + kb + 8 + 2 * tig];
            al[0] = *(const uint32_t*)&sAlo[ra * ASTR + kb + 2 * tig];
            al[1] = *(const uint32_t*)&sAlo[(ra + 8) * ASTR + kb + 2 * tig];
            al[2] = *(const uint32_t*)&sAlo[ra * ASTR + kb + 8 + 2 * tig];
            al[3] = *(const uint32_t*)&sAlo[(ra + 8) * ASTR + kb + 8 + 2 * tig];

            #pragma unroll
            for (int j = 0; j < 12; j++) {
                const int nb = warp_n * 96 + j * 8 + g;
                uint32_t bh[2], bl[2];
                bh[0] = *(const uint32_t*)&sBhi[nb * ASTR + kb + 2 * tig];
                bh[1] = *(const uint32_t*)&sBhi[nb * ASTR + kb + 8 + 2 * tig];
                bl[0] = *(const uint32_t*)&sBlo[nb * ASTR + kb + 2 * tig];
                bl[1] = *(const uint32_t*)&sBlo[nb * ASTR + kb + 8 + 2 * tig];
                mma_bf16(acc[j], ah, bh);
                mma_bf16(acc[j], ah, bl);
                mma_bf16(acc[j], al, bh);
            }
        }
    }

    __syncthreads();   // done with A/B tiles; reuse smem for V staging
    float* sV = (float*)qsm;       // [64][68] fp32 = 17408 B
    const int row_l = warp_m * 16 + g;

    #pragma unroll
    for (int j = 0; j < 12; j++) {
        int nglob = warp_n * 96 + j * 8 + 2 * tig;
        float b0 = bias[nglob], b1 = bias[nglob + 1];
        float v0 = acc[j][0] + b0, v1 = acc[j][1] + b1;
        float v2 = acc[j][2] + b0, v3 = acc[j][3] + b1;
        if (nglob < 128) {
            __nv_bfloat16* dhi = (nglob < 64) ? g_Qhi : g_Khi;
            __nv_bfloat16* dlo = (nglob < 64) ? g_Qlo : g_Klo;
            int col = nglob & 63;
            size_t r0 = (size_t)(m0 + row_l) * DH + col;
            size_t r1 = (size_t)(m0 + row_l + 8) * DH + col;
            *(uint32_t*)&dhi[r0] = pack_hi(v0, v1);
            *(uint32_t*)&dlo[r0] = pack_lo(v0, v1);
            *(uint32_t*)&dhi[r1] = pack_hi(v2, v3);
            *(uint32_t*)&dlo[r1] = pack_lo(v2, v3);
        } else {
            int d = nglob - 128;
            sV[row_l * 68 + d]       = v0;
            sV[row_l * 68 + d + 1]   = v1;
            sV[(row_l + 8) * 68 + d]     = v2;
            sV[(row_l + 8) * 68 + d + 1] = v3;
        }
    }
    __syncthreads();

    // Transposed VT store: thread -> (d, 16-row m segment)
    {
        int d    = tid >> 2;
        int mseg = (tid & 3) * 16;
        int b    = m0 >> 11;
        int s0   = (m0 & 2047) + mseg;
        uint32_t hw[8], lw[8];
        #pragma unroll
        for (int i = 0; i < 8; i++) {
            float c0 = sV[(mseg + 2 * i) * 68 + d];
            float c1 = sV[(mseg + 2 * i + 1) * 68 + d];
            hw[i] = pack_hi(c0, c1);
            lw[i] = pack_lo(c0, c1);
        }
        size_t base = ((size_t)b * DH + d) * SEQ + s0;
        *(uint4*)&g_VThi[base]     = make_uint4(hw[0], hw[1], hw[2], hw[3]);
        *(uint4*)&g_VThi[base + 8] = make_uint4(hw[4], hw[5], hw[6], hw[7]);
        *(uint4*)&g_VTlo[base]     = make_uint4(lw[0], lw[1], lw[2], lw[3]);
        *(uint4*)&g_VTlo[base + 8] = make_uint4(lw[4], lw[5], lw[6], lw[7]);
    }
}

// ---------------------------------------------------------------------------
// Kernel 2: fused masked attention on tensor cores.
// CTA = 128 q-rows x one batch, 8 warps (warp w owns rows w*16..w*16+15),
// k-tiles of 64, double-buffered cp.async K/VT, P kept in registers.
// ---------------------------------------------------------------------------
#define SRB 144                         // smem row stride bytes (72 halves)
#define AT_QH 0
#define AT_QL 18432
#define AT_STAGE 36864                  // 2 stages x (KH,KL,VH,VL) x 9216B
#define AT_SMEM (AT_STAGE + 2 * 36864)  // 110592

__global__ __launch_bounds__(256, 1) void attn_mma_kernel(
    const int* __restrict__ mask,
    float* __restrict__ out)
{
    extern __shared__ char sm[];
    const uint32_t sb = smem_u32(sm);
    const int tid = threadIdx.x;
    const int wid = tid >> 5;
    const int lid = tid & 31;
    const int g   = lid >> 2;
    const int tig = lid & 3;
    const int b   = blockIdx.y;
    const int q0  = blockIdx.x * 128;

    // ---- prologue: Q tile (hi/lo) + stage 0, one cp.async group
    #pragma unroll
    for (int u = 0; u < 8; u++) {
        int c = tid + u * 256;            // 0..2047
        int half = c >> 10;
        int cc = c & 1023;
        int row = cc >> 3, seg = cc & 7;
        uint32_t dst = sb + half * 18432 + row * SRB + seg * 16;
        const __nv_bfloat16* src =
            (half ? g_Qlo : g_Qhi) + (size_t)(b * SEQ + q0 + row) * DH + seg * 8;
        cp16(dst, src);
    }
    {
        const int kt = 0;
        #pragma unroll
        for (int u = 0; u < 8; u++) {
            int c = tid + u * 256;
            int sel = c >> 9;             // 0 KH,1 KL,2 VH,3 VL
            int cc = c & 511;
            int row = cc >> 3, seg = cc & 7;
            uint32_t dst = sb + AT_STAGE + sel * 9216 + row * SRB + seg * 16;
            const __nv_bfloat16* src;
            if (sel == 0)      src = g_Khi  + (size_t)(b * SEQ + kt * 64 + row) * DH + seg * 8;
            else if (sel == 1) src = g_Klo  + (size_t)(b * SEQ + kt * 64 + row) * DH + seg * 8;
            else if (sel == 2) src = g_VThi + ((size_t)b * DH + row) * SEQ + kt * 64 + seg * 8;
            else               src = g_VTlo + ((size_t)b * DH + row) * SEQ + kt * 64 + seg * 8;
            cp16(dst, src);
        }
    }
    CP_COMMIT();

    float acc[8][4];
    #pragma unroll
    for (int j = 0; j < 8; j++)
        #pragma unroll
        for (int i = 0; i < 4; i++) acc[j][i] = 0.0f;
    float l0 = 0.0f, l1 = 0.0f;

    const int mrow = wid * 16;
    const float CEXP = 0.125f * 1.44269504f;
    const int* mr0 = mask + ((size_t)b * SEQ + q0 + mrow + g) * SEQ + 2 * tig;
    const int* mr1 = mr0 + 8 * SEQ;

    #pragma unroll 1
    for (int kt = 0; kt < SEQ / 64; kt++) {
        if (kt + 1 < SEQ / 64) {
            const int kn = kt + 1;
            const int bsel = kn & 1;
            #pragma unroll
            for (int u = 0; u < 8; u++) {
                int c = tid + u * 256;
                int sel = c >> 9;
                int cc = c & 511;
                int row = cc >> 3, seg = cc & 7;
                uint32_t dst = sb + AT_STAGE + bsel * 36864 + sel * 9216 + row * SRB + seg * 16;
                const __nv_bfloat16* src;
                if (sel == 0)      src = g_Khi  + (size_t)(b * SEQ + kn * 64 + row) * DH + seg * 8;
                else if (sel == 1) src = g_Klo  + (size_t)(b * SEQ + kn * 64 + row) * DH + seg * 8;
                else if (sel == 2) src = g_VThi + ((size_t)b * DH + row) * SEQ + kn * 64 + seg * 8;
                else               src = g_VTlo + ((size_t)b * DH + row) * SEQ + kn * 64 + seg * 8;
                cp16(dst, src);
            }
            CP_COMMIT();
            asm volatile("cp.async.wait_group 1;" ::: "memory");
        } else {
            asm volatile("cp.async.wait_group 0;" ::: "memory");
        }
        __syncthreads();

        const char* KH = sm + AT_STAGE + (kt & 1) * 36864;
        const char* KL = KH + 9216;
        const char* VH = KH + 18432;
        const char* VL = KH + 27648;
        const char* QH = sm + AT_QH;
        const char* QL = sm + AT_QL;

        // ---- gemm1: S = Q·K^T (bf16x3)
        float s[8][4];
        #pragma unroll
        for (int j = 0; j < 8; j++)
            #pragma unroll
            for (int i = 0; i < 4; i++) s[j][i] = 0.0f;

        #pragma unroll
        for (int ks = 0; ks < 4; ks++) {
            int ao = (mrow + g) * SRB + ks * 32 + tig * 4;
            uint32_t ah[4], al[4];
            ah[0] = *(const uint32_t*)(QH + ao);
            ah[1] = *(const uint32_t*)(QH + ao + 8 * SRB);
            ah[2] = *(const uint32_t*)(QH + ao + 16);
            ah[3] = *(const uint32_t*)(QH + ao + 8 * SRB + 16);
            al[0] = *(const uint32_t*)(QL + ao);
            al[1] = *(const uint32_t*)(QL + ao + 8 * SRB);
            al[2] = *(const uint32_t*)(QL + ao + 16);
            al[3] = *(const uint32_t*)(QL + ao + 8 * SRB + 16);
            #pragma unroll
            for (int j = 0; j < 8; j++) {
                int bo = (j * 8 + g) * SRB + ks * 32 + tig * 4;
                uint32_t bh[2], bl[2];
                bh[0] = *(const uint32_t*)(KH + bo);
                bh[1] = *(const uint32_t*)(KH + bo + 16);
                bl[0] = *(const uint32_t*)(KL + bo);
                bl[1] = *(const uint32_t*)(KL + bo + 16);
                mma_bf16(s[j], ah, bh);
                mma_bf16(s[j], ah, bl);
                mma_bf16(s[j], al, bh);
            }
        }

        // ---- softmax piece: p = mask ? 1 : 2^(s*0.125*log2e); accumulate l
        #pragma unroll
        for (int j = 0; j < 8; j++) {
            int2 m0v = *(const int2*)(mr0 + kt * 64 + j * 8);
            int2 m1v = *(const int2*)(mr1 + kt * 64 + j * 8);
            float p0 = (m0v.x == 1) ? 1.0f : fexp2(s[j][0] * CEXP);
            float p1 = (m0v.y == 1) ? 1.0f : fexp2(s[j][1] * CEXP);
            float p2 = (m1v.x == 1) ? 1.0f : fexp2(s[j][2] * CEXP);
            float p3 = (m1v.y == 1) ? 1.0f : fexp2(s[j][3] * CEXP);
            s[j][0] = p0; s[j][1] = p1; s[j][2] = p2; s[j][3] = p3;
            l0 += p0 + p1;
            l1 += p2 + p3;
        }

        // ---- gemm2: acc += P·V  (P from regs, bf16x3)
        #pragma unroll
        for (int k2 = 0; k2 < 4; k2++) {
            const float* pa = s[2 * k2];
            const float* pb = s[2 * k2 + 1];
            uint32_t ph[4], pl[4];
            ph[0] = pack_hi(pa[0], pa[1]);  pl[0] = pack_lo(pa[0], pa[1]);
            ph[1] = pack_hi(pa[2], pa[3]);  pl[1] = pack_lo(pa[2], pa[3]);
            ph[2] = pack_hi(pb[0], pb[1]);  pl[2] = pack_lo(pb[0], pb[1]);
            ph[3] = pack_hi(pb[2], pb[3]);  pl[3] = pack_lo(pb[2], pb[3]);
            #pragma unroll
            for (int j2 = 0; j2 < 8; j2++) {
                int vo = (j2 * 8 + g) * SRB + k2 * 32 + tig * 4;
                uint32_t vh[2], vl[2];
                vh[0] = *(const uint32_t*)(VH + vo);
                vh[1] = *(const uint32_t*)(VH + vo + 16);
                vl[0] = *(const uint32_t*)(VL + vo);
                vl[1] = *(const uint32_t*)(VL + vo + 16);
                mma_bf16(acc[j2], ph, vh);
                mma_bf16(acc[j2], ph, vl);
                mma_bf16(acc[j2], pl, vh);
            }
        }
        __syncthreads();
    }

    // ---- epilogue: reduce l across the 4 lanes sharing a row, divide, store
    l0 += __shfl_xor_sync(0xffffffffu, l0, 1);
    l0 += __shfl_xor_sync(0xffffffffu, l0, 2);
    l1 += __shfl_xor_sync(0xffffffffu, l1, 1);
    l1 += __shfl_xor_sync(0xffffffffu, l1, 2);
    float inv0 = 1.0f / l0, inv1 = 1.0f / l1;

    size_t r0 = (size_t)(b * SEQ + q0 + mrow + g) * DH;
    size_t r1 = r0 + 8 * DH;
    #pragma unroll
    for (int j2 = 0; j2 < 8; j2++) {
        int col = j2 * 8 + 2 * tig;
        *(float2*)&out[r0 + col] = make_float2(acc[j2][0] * inv0, acc[j2][1] * inv0);
        *(float2*)&out[r1 + col] = make_float2(acc[j2][2] * inv1, acc[j2][3] * inv1);
    }
}

// ---------------------------------------------------------------------------
extern "C" void kernel_launch(void* const* d_in, const int* in_sizes, int n_in,
                              void* d_out, int out_size)
{
    const float* x    = (const float*)d_in[0];
    const int*   mask = (const int*)d_in[1];
    const float* W    = (const float*)d_in[2];
    const float* bias = (const float*)d_in[3];
    float* out = (float*)d_out;

    (void)in_sizes; (void)n_in; (void)out_size;

    static int attr_set = 0;
    if (!attr_set) {
        cudaFuncSetAttribute(attn_mma_kernel,
                             cudaFuncAttributeMaxDynamicSharedMemorySize, AT_SMEM);
        attr_set = 1;
    }

    wconv_kernel<<<(192 * EMB) / 256, 256>>>(W);
    qkv_mma_kernel<<<NROWS / 64, 256>>>(x, bias);

    dim3 g2(SEQ / 128, BATCH);
    attn_mma_kernel<<<g2, 256, AT_SMEM>>>(mask, out);
}

// round 5
// speedup vs baseline: 2.0727x; 1.1133x over previous
#include <cuda_runtime.h>
#include <cuda_fp16.h>
#include <math.h>
#include <stdint.h>

#define BATCH 8
#define SEQ   2048
#define EMB   1024
#define DH    64
#define NROWS (BATCH * SEQ)   // 16384

// Pre-split fp16 operands produced by the QKV kernel.
__device__ __half g_Qhi[NROWS * DH];
__device__ __half g_Qlo[NROWS * DH];
__device__ __half g_Khi[NROWS * DH];
__device__ __half g_Klo[NROWS * DH];
__device__ __half g_VThi[BATCH * DH * SEQ];  // [b][d][s]
__device__ __half g_VTlo[BATCH * DH * SEQ];
__device__ __half g_WhiT[192 * EMB];          // [n][k]
__device__ __half g_WloT[192 * EMB];

// ---------------------------------------------------------------------------
// helpers
// ---------------------------------------------------------------------------
__device__ __forceinline__ void mma_f16(float* c, const uint32_t* a, const uint32_t* b) {
    asm volatile(
        "mma.sync.aligned.m16n8k16.row.col.f32.f16.f16.f32 "
        "{%0,%1,%2,%3}, {%4,%5,%6,%7}, {%8,%9}, {%0,%1,%2,%3};"
        : "+f"(c[0]), "+f"(c[1]), "+f"(c[2]), "+f"(c[3])
        : "r"(a[0]), "r"(a[1]), "r"(a[2]), "r"(a[3]), "r"(b[0]), "r"(b[1]));
}

__device__ __forceinline__ void ldsm4(uint32_t* r, uint32_t a) {
    asm volatile("ldmatrix.sync.aligned.m8n8.x4.shared.b16 {%0,%1,%2,%3}, [%4];"
        : "=r"(r[0]), "=r"(r[1]), "=r"(r[2]), "=r"(r[3]) : "r"(a));
}

__device__ __forceinline__ uint32_t smem_u32(const void* p) {
    uint32_t a;
    asm("{ .reg .u64 t; cvta.to.shared.u64 t, %1; cvt.u32.u64 %0, t; }"
        : "=r"(a) : "l"(p));
    return a;
}

__device__ __forceinline__ void cp16(uint32_t dst, const void* src) {
    asm volatile("cp.async.cg.shared.global [%0], [%1], 16;" :: "r"(dst), "l"(src));
}
#define CP_COMMIT() asm volatile("cp.async.commit_group;" ::: "memory")

// Fast 2^t on the FMA pipe (abs err ~2.4e-6 for |t| <= ~12).
__device__ __forceinline__ float fexp2(float t) {
    float z = t + 12582912.0f;
    float f = t - (z - 12582912.0f);
    int   e = __float_as_int(z) << 23;
    float p = 0.0013333558f;
    p = fmaf(p, f, 0.0096181291f);
    p = fmaf(p, f, 0.0555041087f);
    p = fmaf(p, f, 0.2402265070f);
    p = fmaf(p, f, 0.6931471806f);
    p = fmaf(p, f, 1.0f);
    return __int_as_float(__float_as_int(p) + e);
}

__device__ __forceinline__ uint32_t hpack_hi(float a, float b) {
    __half2 h = __floats2half2_rn(a, b);
    return *(uint32_t*)&h;
}
__device__ __forceinline__ uint32_t hpack_lo(float a, float b) {
    __half ha = __float2half_rn(a), hb = __float2half_rn(b);
    __half2 l = __halves2half2(__float2half_rn(a - __half2float(ha)),
                               __float2half_rn(b - __half2float(hb)));
    return *(uint32_t*)&l;
}

// ---------------------------------------------------------------------------
// Kernel 0: W [1024,192] fp32 -> transposed hi/lo fp16 [192][1024]
// ---------------------------------------------------------------------------
__global__ void wconv_kernel(const float* __restrict__ W) {
    int idx = blockIdx.x * 256 + threadIdx.x;
    int k = idx & 1023;
    int n = idx >> 10;
    float w = W[(size_t)k * 192 + n];
    __half hi = __float2half_rn(w);
    g_WhiT[(size_t)n * EMB + k] = hi;
    g_WloT[(size_t)n * EMB + k] = __float2half_rn(w - __half2float(hi));
}

// ---------------------------------------------------------------------------
// Kernel 1: QKV projection (mma.sync fp16x3). Emits pre-split fp16 hi/lo
// Q, K (row-major) and transposed VT (via smem staging).
// ---------------------------------------------------------------------------
#define ASTR 40
#define QSM_AHI 0
#define QSM_ALO 5120
#define QSM_BHI 10240
#define QSM_BLO 25600
#define QSM_TOT 40960

__global__ __launch_bounds__(256) void qkv_mma_kernel(
    const float* __restrict__ x,
    const float* __restrict__ bias)
{
    __shared__ char qsm[QSM_TOT];
    __half* sAhi = (__half*)(qsm + QSM_AHI);
    __half* sAlo = (__half*)(qsm + QSM_ALO);
    __half* sBhi = (__half*)(qsm + QSM_BHI);
    __half* sBlo = (__half*)(qsm + QSM_BLO);

    const int tid = threadIdx.x;
    const int wid = tid >> 5;
    const int lid = tid & 31;
    const int g   = lid >> 2;
    const int tig = lid & 3;
    const int warp_m = wid & 3;
    const int warp_n = wid >> 2;
    const int m0 = blockIdx.x * 64;

    float acc[12][4];
    #pragma unroll
    for (int j = 0; j < 12; j++)
        #pragma unroll
        for (int i = 0; i < 4; i++) acc[j][i] = 0.0f;

    for (int k0 = 0; k0 < EMB; k0 += 32) {
        __syncthreads();
        #pragma unroll
        for (int u = 0; u < 2; u++) {
            int id  = tid + u * 256;
            int row = id >> 3;
            int c4  = id & 7;
            float4 v = *(const float4*)&x[(size_t)(m0 + row) * EMB + k0 + c4 * 4];
            int e = row * ASTR + c4 * 4;
            *(uint32_t*)&sAhi[e]     = hpack_hi(v.x, v.y);
            *(uint32_t*)&sAhi[e + 2] = hpack_hi(v.z, v.w);
            *(uint32_t*)&sAlo[e]     = hpack_lo(v.x, v.y);
            *(uint32_t*)&sAlo[e + 2] = hpack_lo(v.z, v.w);
        }
        #pragma unroll
        for (int u = 0; u < 6; u++) {
            int id  = tid + u * 256;
            int row = id >> 3;
            int c   = id & 7;
            uint2 vh = *(const uint2*)&g_WhiT[(size_t)row * EMB + k0 + c * 4];
            uint2 vl = *(const uint2*)&g_WloT[(size_t)row * EMB + k0 + c * 4];
            int e = row * ASTR + c * 4;
            *(uint2*)&sBhi[e] = vh;
            *(uint2*)&sBlo[e] = vl;
        }
        __syncthreads();

        #pragma unroll
        for (int ks = 0; ks < 2; ks++) {
            const int kb = ks * 16;
            const int ra = warp_m * 16 + g;
            uint32_t ah[4], al[4];
            ah[0] = *(const uint32_t*)&sAhi[ra * ASTR + kb + 2 * tig];
            ah[1] = *(const uint32_t*)&sAhi[(ra + 8) * ASTR + kb + 2 * tig];
            ah[2] = *(const uint32_t*)&sAhi[ra * ASTR + kb + 8 + 2 * tig];
            ah[3] = *(const uint32_t*)&sAhi[(ra + 8) * ASTR + kb + 8 + 2 * tig];
            al[0] = *(const uint32_t*)&sAlo[ra * ASTR + kb + 2 * tig];
            al[1] = *(const uint32_t*)&sAlo[(ra + 8) * ASTR + kb + 2 * tig];
            al[2] = *(const uint32_t*)&sAlo[ra * ASTR + kb + 8 + 2 * tig];
            al[3] = *(const uint32_t*)&sAlo[(ra + 8) * ASTR + kb + 8 + 2 * tig];

            #pragma unroll
            for (int j = 0; j < 12; j++) {
                const int nb = warp_n * 96 + j * 8 + g;
                uint32_t bh[2], bl[2];
                bh[0] = *(const uint32_t*)&sBhi[nb * ASTR + kb + 2 * tig];
                bh[1] = *(const uint32_t*)&sBhi[nb * ASTR + kb + 8 + 2 * tig];
                bl[0] = *(const uint32_t*)&sBlo[nb * ASTR + kb + 2 * tig];
                bl[1] = *(const uint32_t*)&sBlo[nb * ASTR + kb + 8 + 2 * tig];
                mma_f16(acc[j], ah, bh);
                mma_f16(acc[j], ah, bl);
                mma_f16(acc[j], al, bh);
            }
        }
    }

    __syncthreads();   // done with A/B tiles; reuse smem for V staging
    float* sV = (float*)qsm;       // [64][68] fp32 = 17408 B
    const int row_l = warp_m * 16 + g;

    #pragma unroll
    for (int j = 0; j < 12; j++) {
        int nglob = warp_n * 96 + j * 8 + 2 * tig;
        float b0 = bias[nglob], b1 = bias[nglob + 1];
        float v0 = acc[j][0] + b0, v1 = acc[j][1] + b1;
        float v2 = acc[j][2] + b0, v3 = acc[j][3] + b1;
        if (nglob < 128) {
            __half* dhi = (nglob < 64) ? g_Qhi : g_Khi;
            __half* dlo = (nglob < 64) ? g_Qlo : g_Klo;
            int col = nglob & 63;
            size_t r0 = (size_t)(m0 + row_l) * DH + col;
            size_t r1 = (size_t)(m0 + row_l + 8) * DH + col;
            *(uint32_t*)&dhi[r0] = hpack_hi(v0, v1);
            *(uint32_t*)&dlo[r0] = hpack_lo(v0, v1);
            *(uint32_t*)&dhi[r1] = hpack_hi(v2, v3);
            *(uint32_t*)&dlo[r1] = hpack_lo(v2, v3);
        } else {
            int d = nglob - 128;
            sV[row_l * 68 + d]       = v0;
            sV[row_l * 68 + d + 1]   = v1;
            sV[(row_l + 8) * 68 + d]     = v2;
            sV[(row_l + 8) * 68 + d + 1] = v3;
        }
    }
    __syncthreads();

    // Transposed VT store: thread -> (d, 16-row m segment)
    {
        int d    = tid >> 2;
        int mseg = (tid & 3) * 16;
        int b    = m0 >> 11;
        int s0   = (m0 & 2047) + mseg;
        uint32_t hw[8], lw[8];
        #pragma unroll
        for (int i = 0; i < 8; i++) {
            float c0 = sV[(mseg + 2 * i) * 68 + d];
            float c1 = sV[(mseg + 2 * i + 1) * 68 + d];
            hw[i] = hpack_hi(c0, c1);
            lw[i] = hpack_lo(c0, c1);
        }
        size_t base = ((size_t)b * DH + d) * SEQ + s0;
        *(uint4*)&g_VThi[base]     = make_uint4(hw[0], hw[1], hw[2], hw[3]);
        *(uint4*)&g_VThi[base + 8] = make_uint4(hw[4], hw[5], hw[6], hw[7]);
        *(uint4*)&g_VTlo[base]     = make_uint4(lw[0], lw[1], lw[2], lw[3]);
        *(uint4*)&g_VTlo[base + 8] = make_uint4(lw[4], lw[5], lw[6], lw[7]);
    }
}

// ---------------------------------------------------------------------------
// Kernel 2: fused masked attention on tensor cores (fp16, ldmatrix).
// CTA = 128 q-rows x one batch, 8 warps; k-tiles of 64, double-buffered
// cp.async K/VT; P in registers (unsplit fp16, gemm2 2-term).
// ---------------------------------------------------------------------------
#define SRB 144                         // smem row stride bytes (72 halves)
#define AT_QH 0
#define AT_QL 18432
#define AT_STAGE 36864                  // 2 stages x (KH,KL,VH,VL) x 9216B
#define AT_SMEM (AT_STAGE + 2 * 36864)  // 110592

__global__ __launch_bounds__(256, 1) void attn_mma_kernel(
    const int* __restrict__ mask,
    float* __restrict__ out)
{
    extern __shared__ char sm[];
    const uint32_t sb = smem_u32(sm);
    const int tid = threadIdx.x;
    const int wid = tid >> 5;
    const int lid = tid & 31;
    const int g   = lid >> 2;
    const int tig = lid & 3;
    const int b   = blockIdx.y;
    const int q0  = blockIdx.x * 128;

    // ---- prologue: Q tile (hi/lo) + stage 0, one cp.async group
    #pragma unroll
    for (int u = 0; u < 8; u++) {
        int c = tid + u * 256;            // 0..2047
        int half_ = c >> 10;
        int cc = c & 1023;
        int row = cc >> 3, seg = cc & 7;
        uint32_t dst = sb + half_ * 18432 + row * SRB + seg * 16;
        const __half* src =
            (half_ ? g_Qlo : g_Qhi) + (size_t)(b * SEQ + q0 + row) * DH + seg * 8;
        cp16(dst, src);
    }
    {
        const int kt = 0;
        #pragma unroll
        for (int u = 0; u < 8; u++) {
            int c = tid + u * 256;
            int sel = c >> 9;             // 0 KH,1 KL,2 VH,3 VL
            int cc = c & 511;
            int row = cc >> 3, seg = cc & 7;
            uint32_t dst = sb + AT_STAGE + sel * 9216 + row * SRB + seg * 16;
            const __half* src;
            if (sel == 0)      src = g_Khi  + (size_t)(b * SEQ + kt * 64 + row) * DH + seg * 8;
            else if (sel == 1) src = g_Klo  + (size_t)(b * SEQ + kt * 64 + row) * DH + seg * 8;
            else if (sel == 2) src = g_VThi + ((size_t)b * DH + row) * SEQ + kt * 64 + seg * 8;
            else               src = g_VTlo + ((size_t)b * DH + row) * SEQ + kt * 64 + seg * 8;
            cp16(dst, src);
        }
    }
    CP_COMMIT();

    float acc[8][4];
    #pragma unroll
    for (int j = 0; j < 8; j++)
        #pragma unroll
        for (int i = 0; i < 4; i++) acc[j][i] = 0.0f;
    float l0 = 0.0f, l1 = 0.0f;

    const int mrow = wid * 16;
    const float CEXP = 0.125f * 1.44269504f;
    const int* mr0 = mask + ((size_t)b * SEQ + q0 + mrow + g) * SEQ + 2 * tig;
    const int* mr1 = mr0 + 8 * SEQ;

    // ldmatrix per-lane address components
    const int rowA  = mrow + (lid & 7) + ((lid >> 3) & 1) * 8;  // A: 16x32B block
    const int byteA = (lid >> 4) * 16;
    const int rowB  = (lid & 7) + (lid >> 4) * 8;               // B/V: j-pair block
    const int byteB = ((lid >> 3) & 1) * 16;
    const uint32_t aQH = sb + AT_QH + rowA * SRB + byteA;
    const uint32_t aQL = aQH + 18432;
    const uint32_t aBV = rowB * SRB + byteB;                    // add stage base

    #pragma unroll 1
    for (int kt = 0; kt < SEQ / 64; kt++) {
        if (kt + 1 < SEQ / 64) {
            const int kn = kt + 1;
            const int bsel = kn & 1;
            #pragma unroll
            for (int u = 0; u < 8; u++) {
                int c = tid + u * 256;
                int sel = c >> 9;
                int cc = c & 511;
                int row = cc >> 3, seg = cc & 7;
                uint32_t dst = sb + AT_STAGE + bsel * 36864 + sel * 9216 + row * SRB + seg * 16;
                const __half* src;
                if (sel == 0)      src = g_Khi  + (size_t)(b * SEQ + kn * 64 + row) * DH + seg * 8;
                else if (sel == 1) src = g_Klo  + (size_t)(b * SEQ + kn * 64 + row) * DH + seg * 8;
                else if (sel == 2) src = g_VThi + ((size_t)b * DH + row) * SEQ + kn * 64 + seg * 8;
                else               src = g_VTlo + ((size_t)b * DH + row) * SEQ + kn * 64 + seg * 8;
                cp16(dst, src);
            }
            CP_COMMIT();
            asm volatile("cp.async.wait_group 1;" ::: "memory");
        } else {
            asm volatile("cp.async.wait_group 0;" ::: "memory");
        }
        __syncthreads();

        const uint32_t stg = sb + AT_STAGE + (kt & 1) * 36864;
        const uint32_t aKH = stg + aBV;
        const uint32_t aKL = aKH + 9216;
        const uint32_t aVH = aKH + 18432;
        const uint32_t aVL = aKH + 27648;

        // ---- gemm1: S = Q·K^T (fp16 x3)
        float s[8][4];
        #pragma unroll
        for (int j = 0; j < 8; j++)
            #pragma unroll
            for (int i = 0; i < 4; i++) s[j][i] = 0.0f;

        #pragma unroll
        for (int ks = 0; ks < 4; ks++) {
            uint32_t ah[4], al[4];
            ldsm4(ah, aQH + ks * 32);
            ldsm4(al, aQL + ks * 32);
            #pragma unroll
            for (int jp = 0; jp < 4; jp++) {
                uint32_t bh[4], bl[4];
                ldsm4(bh, aKH + jp * (16 * SRB) + ks * 32);
                ldsm4(bl, aKL + jp * (16 * SRB) + ks * 32);
                mma_f16(s[2 * jp],     ah, bh);
                mma_f16(s[2 * jp],     ah, bl);
                mma_f16(s[2 * jp],     al, bh);
                mma_f16(s[2 * jp + 1], ah, bh + 2);
                mma_f16(s[2 * jp + 1], ah, bl + 2);
                mma_f16(s[2 * jp + 1], al, bh + 2);
            }
        }

        // ---- softmax piece: p = mask ? 1 : 2^(s*0.125*log2e); accumulate l
        #pragma unroll
        for (int j = 0; j < 8; j++) {
            int2 m0v = *(const int2*)(mr0 + kt * 64 + j * 8);
            int2 m1v = *(const int2*)(mr1 + kt * 64 + j * 8);
            float p0 = (m0v.x == 1) ? 1.0f : fexp2(s[j][0] * CEXP);
            float p1 = (m0v.y == 1) ? 1.0f : fexp2(s[j][1] * CEXP);
            float p2 = (m1v.x == 1) ? 1.0f : fexp2(s[j][2] * CEXP);
            float p3 = (m1v.y == 1) ? 1.0f : fexp2(s[j][3] * CEXP);
            s[j][0] = p0; s[j][1] = p1; s[j][2] = p2; s[j][3] = p3;
            l0 += p0 + p1;
            l1 += p2 + p3;
        }

        // ---- gemm2: acc += P·V  (P unsplit fp16, V hi/lo: 2-term)
        #pragma unroll
        for (int k2 = 0; k2 < 4; k2++) {
            const float* pa = s[2 * k2];
            const float* pb = s[2 * k2 + 1];
            uint32_t ph[4];
            ph[0] = hpack_hi(pa[0], pa[1]);
            ph[1] = hpack_hi(pa[2], pa[3]);
            ph[2] = hpack_hi(pb[0], pb[1]);
            ph[3] = hpack_hi(pb[2], pb[3]);
            #pragma unroll
            for (int jp = 0; jp < 4; jp++) {
                uint32_t vh[4], vl[4];
                ldsm4(vh, aVH + jp * (16 * SRB) + k2 * 32);
                ldsm4(vl, aVL + jp * (16 * SRB) + k2 * 32);
                mma_f16(acc[2 * jp],     ph, vh);
                mma_f16(acc[2 * jp],     ph, vl);
                mma_f16(acc[2 * jp + 1], ph, vh + 2);
                mma_f16(acc[2 * jp + 1], ph, vl + 2);
            }
        }
        __syncthreads();
    }

    // ---- epilogue: reduce l across the 4 lanes sharing a row, divide, store
    l0 += __shfl_xor_sync(0xffffffffu, l0, 1);
    l0 += __shfl_xor_sync(0xffffffffu, l0, 2);
    l1 += __shfl_xor_sync(0xffffffffu, l1, 1);
    l1 += __shfl_xor_sync(0xffffffffu, l1, 2);
    float inv0 = 1.0f / l0, inv1 = 1.0f / l1;

    size_t r0 = (size_t)(b * SEQ + q0 + mrow + g) * DH;
    size_t r1 = r0 + 8 * DH;
    #pragma unroll
    for (int j2 = 0; j2 < 8; j2++) {
        int col = j2 * 8 + 2 * tig;
        *(float2*)&out[r0 + col] = make_float2(acc[j2][0] * inv0, acc[j2][1] * inv0);
        *(float2*)&out[r1 + col] = make_float2(acc[j2][2] * inv1, acc[j2][3] * inv1);
    }
}

// ---------------------------------------------------------------------------
extern "C" void kernel_launch(void* const* d_in, const int* in_sizes, int n_in,
                              void* d_out, int out_size)
{
    const float* x    = (const float*)d_in[0];
    const int*   mask = (const int*)d_in[1];
    const float* W    = (const float*)d_in[2];
    const float* bias = (const float*)d_in[3];
    float* out = (float*)d_out;

    (void)in_sizes; (void)n_in; (void)out_size;

    static int attr_set = 0;
    if (!attr_set) {
        cudaFuncSetAttribute(attn_mma_kernel,
                             cudaFuncAttributeMaxDynamicSharedMemorySize, AT_SMEM);
        attr_set = 1;
    }

    wconv_kernel<<<(192 * EMB) / 256, 256>>>(W);
    qkv_mma_kernel<<<NROWS / 64, 256>>>(x, bias);

    dim3 g2(SEQ / 128, BATCH);
    attn_mma_kernel<<<g2, 256, AT_SMEM>>>(mask, out);
}

// round 6
// speedup vs baseline: 2.2853x; 1.1026x over previous
#include <cuda_runtime.h>
#include <cuda_fp16.h>
#include <math.h>
#include <stdint.h>

#define BATCH 8
#define SEQ   2048
#define EMB   1024
#define DH    64
#define NROWS (BATCH * SEQ)   // 16384

// Pre-split fp16 operands produced by the QKV kernel.
__device__ __half g_Qhi[NROWS * DH];
__device__ __half g_Qlo[NROWS * DH];
__device__ __half g_Khi[NROWS * DH];
__device__ __half g_VThi[BATCH * DH * SEQ];  // [b][d][s]
__device__ __half g_WhiT[192 * EMB];          // [n][k]
__device__ __half g_WloT[192 * EMB];

// ---------------------------------------------------------------------------
// helpers
// ---------------------------------------------------------------------------
__device__ __forceinline__ void mma_f16(float* c, const uint32_t* a, const uint32_t* b) {
    asm volatile(
        "mma.sync.aligned.m16n8k16.row.col.f32.f16.f16.f32 "
        "{%0,%1,%2,%3}, {%4,%5,%6,%7}, {%8,%9}, {%0,%1,%2,%3};"
        : "+f"(c[0]), "+f"(c[1]), "+f"(c[2]), "+f"(c[3])
        : "r"(a[0]), "r"(a[1]), "r"(a[2]), "r"(a[3]), "r"(b[0]), "r"(b[1]));
}

__device__ __forceinline__ void ldsm4(uint32_t* r, uint32_t a) {
    asm volatile("ldmatrix.sync.aligned.m8n8.x4.shared.b16 {%0,%1,%2,%3}, [%4];"
        : "=r"(r[0]), "=r"(r[1]), "=r"(r[2]), "=r"(r[3]) : "r"(a));
}

__device__ __forceinline__ uint32_t smem_u32(const void* p) {
    uint32_t a;
    asm("{ .reg .u64 t; cvta.to.shared.u64 t, %1; cvt.u32.u64 %0, t; }"
        : "=r"(a) : "l"(p));
    return a;
}

__device__ __forceinline__ void cp16(uint32_t dst, const void* src) {
    asm volatile("cp.async.cg.shared.global [%0], [%1], 16;" :: "r"(dst), "l"(src));
}
#define CP_COMMIT() asm volatile("cp.async.commit_group;" ::: "memory")

// Fast 2^t on the FMA pipe (abs err ~2.4e-6 for |t| <= ~12).
__device__ __forceinline__ float fexp2(float t) {
    float z = t + 12582912.0f;
    float f = t - (z - 12582912.0f);
    int   e = __float_as_int(z) << 23;
    float p = 0.0013333558f;
    p = fmaf(p, f, 0.0096181291f);
    p = fmaf(p, f, 0.0555041087f);
    p = fmaf(p, f, 0.2402265070f);
    p = fmaf(p, f, 0.6931471806f);
    p = fmaf(p, f, 1.0f);
    return __int_as_float(__float_as_int(p) + e);
}

__device__ __forceinline__ uint32_t hpack_hi(float a, float b) {
    __half2 h = __floats2half2_rn(a, b);
    return *(uint32_t*)&h;
}
__device__ __forceinline__ uint32_t hpack_lo(float a, float b) {
    __half ha = __float2half_rn(a), hb = __float2half_rn(b);
    __half2 l = __halves2half2(__float2half_rn(a - __half2float(ha)),
                               __float2half_rn(b - __half2float(hb)));
    return *(uint32_t*)&l;
}

// ---------------------------------------------------------------------------
// Kernel 0: W [1024,192] fp32 -> transposed hi/lo fp16 [192][1024]
// ---------------------------------------------------------------------------
__global__ void wconv_kernel(const float* __restrict__ W) {
    int idx = blockIdx.x * 256 + threadIdx.x;
    int k = idx & 1023;
    int n = idx >> 10;
    float w = W[(size_t)k * 192 + n];
    __half hi = __float2half_rn(w);
    g_WhiT[(size_t)n * EMB + k] = hi;
    g_WloT[(size_t)n * EMB + k] = __float2half_rn(w - __half2float(hi));
}

// ---------------------------------------------------------------------------
// Kernel 1: QKV projection (mma.sync fp16x3). Emits split Q (hi/lo),
// unsplit-hi K, and transposed VT-hi (via smem staging).
// ---------------------------------------------------------------------------
#define ASTR 40
#define QSM_AHI 0
#define QSM_ALO 5120
#define QSM_BHI 10240
#define QSM_BLO 25600
#define QSM_TOT 40960

__global__ __launch_bounds__(256) void qkv_mma_kernel(
    const float* __restrict__ x,
    const float* __restrict__ bias)
{
    __shared__ char qsm[QSM_TOT];
    __half* sAhi = (__half*)(qsm + QSM_AHI);
    __half* sAlo = (__half*)(qsm + QSM_ALO);
    __half* sBhi = (__half*)(qsm + QSM_BHI);
    __half* sBlo = (__half*)(qsm + QSM_BLO);

    const int tid = threadIdx.x;
    const int lid = tid & 31;
    const int wid = tid >> 5;
    const int g   = lid >> 2;
    const int tig = lid & 3;
    const int warp_m = wid & 3;
    const int warp_n = wid >> 2;
    const int m0 = blockIdx.x * 64;

    float acc[12][4];
    #pragma unroll
    for (int j = 0; j < 12; j++)
        #pragma unroll
        for (int i = 0; i < 4; i++) acc[j][i] = 0.0f;

    for (int k0 = 0; k0 < EMB; k0 += 32) {
        __syncthreads();
        #pragma unroll
        for (int u = 0; u < 2; u++) {
            int id  = tid + u * 256;
            int row = id >> 3;
            int c4  = id & 7;
            float4 v = *(const float4*)&x[(size_t)(m0 + row) * EMB + k0 + c4 * 4];
            int e = row * ASTR + c4 * 4;
            *(uint32_t*)&sAhi[e]     = hpack_hi(v.x, v.y);
            *(uint32_t*)&sAhi[e + 2] = hpack_hi(v.z, v.w);
            *(uint32_t*)&sAlo[e]     = hpack_lo(v.x, v.y);
            *(uint32_t*)&sAlo[e + 2] = hpack_lo(v.z, v.w);
        }
        #pragma unroll
        for (int u = 0; u < 6; u++) {
            int id  = tid + u * 256;
            int row = id >> 3;
            int c   = id & 7;
            uint2 vh = *(const uint2*)&g_WhiT[(size_t)row * EMB + k0 + c * 4];
            uint2 vl = *(const uint2*)&g_WloT[(size_t)row * EMB + k0 + c * 4];
            int e = row * ASTR + c * 4;
            *(uint2*)&sBhi[e] = vh;
            *(uint2*)&sBlo[e] = vl;
        }
        __syncthreads();

        #pragma unroll
        for (int ks = 0; ks < 2; ks++) {
            const int kb = ks * 16;
            const int ra = warp_m * 16 + g;
            uint32_t ah[4], al[4];
            ah[0] = *(const uint32_t*)&sAhi[ra * ASTR + kb + 2 * tig];
            ah[1] = *(const uint32_t*)&sAhi[(ra + 8) * ASTR + kb + 2 * tig];
            ah[2] = *(const uint32_t*)&sAhi[ra * ASTR + kb + 8 + 2 * tig];
            ah[3] = *(const uint32_t*)&sAhi[(ra + 8) * ASTR + kb + 8 + 2 * tig];
            al[0] = *(const uint32_t*)&sAlo[ra * ASTR + kb + 2 * tig];
            al[1] = *(const uint32_t*)&sAlo[(ra + 8) * ASTR + kb + 2 * tig];
            al[2] = *(const uint32_t*)&sAlo[ra * ASTR + kb + 8 + 2 * tig];
            al[3] = *(const uint32_t*)&sAlo[(ra + 8) * ASTR + kb + 8 + 2 * tig];

            #pragma unroll
            for (int j = 0; j < 12; j++) {
                const int nb = warp_n * 96 + j * 8 + g;
                uint32_t bh[2], bl[2];
                bh[0] = *(const uint32_t*)&sBhi[nb * ASTR + kb + 2 * tig];
                bh[1] = *(const uint32_t*)&sBhi[nb * ASTR + kb + 8 + 2 * tig];
                bl[0] = *(const uint32_t*)&sBlo[nb * ASTR + kb + 2 * tig];
                bl[1] = *(const uint32_t*)&sBlo[nb * ASTR + kb + 8 + 2 * tig];
                mma_f16(acc[j], ah, bh);
                mma_f16(acc[j], ah, bl);
                mma_f16(acc[j], al, bh);
            }
        }
    }

    __syncthreads();   // done with A/B tiles; reuse smem for V staging
    float* sV = (float*)qsm;       // [64][68] fp32 = 17408 B
    const int row_l = warp_m * 16 + g;

    #pragma unroll
    for (int j = 0; j < 12; j++) {
        int nglob = warp_n * 96 + j * 8 + 2 * tig;
        float b0 = bias[nglob], b1 = bias[nglob + 1];
        float v0 = acc[j][0] + b0, v1 = acc[j][1] + b1;
        float v2 = acc[j][2] + b0, v3 = acc[j][3] + b1;
        if (nglob < 64) {
            size_t r0 = (size_t)(m0 + row_l) * DH + nglob;
            size_t r1 = (size_t)(m0 + row_l + 8) * DH + nglob;
            *(uint32_t*)&g_Qhi[r0] = hpack_hi(v0, v1);
            *(uint32_t*)&g_Qlo[r0] = hpack_lo(v0, v1);
            *(uint32_t*)&g_Qhi[r1] = hpack_hi(v2, v3);
            *(uint32_t*)&g_Qlo[r1] = hpack_lo(v2, v3);
        } else if (nglob < 128) {
            int col = nglob - 64;
            size_t r0 = (size_t)(m0 + row_l) * DH + col;
            size_t r1 = (size_t)(m0 + row_l + 8) * DH + col;
            *(uint32_t*)&g_Khi[r0] = hpack_hi(v0, v1);
            *(uint32_t*)&g_Khi[r1] = hpack_hi(v2, v3);
        } else {
            int d = nglob - 128;
            sV[row_l * 68 + d]       = v0;
            sV[row_l * 68 + d + 1]   = v1;
            sV[(row_l + 8) * 68 + d]     = v2;
            sV[(row_l + 8) * 68 + d + 1] = v3;
        }
    }
    __syncthreads();

    // Transposed VT store: thread -> (d, 16-row m segment)
    {
        int d    = tid >> 2;
        int mseg = (tid & 3) * 16;
        int b    = m0 >> 11;
        int s0   = (m0 & 2047) + mseg;
        uint32_t hw[8];
        #pragma unroll
        for (int i = 0; i < 8; i++) {
            float c0 = sV[(mseg + 2 * i) * 68 + d];
            float c1 = sV[(mseg + 2 * i + 1) * 68 + d];
            hw[i] = hpack_hi(c0, c1);
        }
        size_t base = ((size_t)b * DH + d) * SEQ + s0;
        *(uint4*)&g_VThi[base]     = make_uint4(hw[0], hw[1], hw[2], hw[3]);
        *(uint4*)&g_VThi[base + 8] = make_uint4(hw[4], hw[5], hw[6], hw[7]);
    }
}

// ---------------------------------------------------------------------------
// Kernel 2: fused masked attention on tensor cores (fp16, ldmatrix).
// CTA = 128 q-rows x one batch, 8 warps; k-tiles of 64, double-buffered
// cp.async K-hi/VT-hi; gemm1 = (Qhi+Qlo)·Khi, gemm2 = P_fp16·Vhi.
// ---------------------------------------------------------------------------
#define SRB 144                         // smem row stride bytes (72 halves)
#define AT_QH 0
#define AT_QL 18432
#define AT_STAGE 36864                  // 2 stages x (KH,VH) x 9216B
#define AT_SMEM (AT_STAGE + 2 * 18432)  // 73728

__global__ __launch_bounds__(256, 1) void attn_mma_kernel(
    const int* __restrict__ mask,
    float* __restrict__ out)
{
    extern __shared__ char sm[];
    const uint32_t sb = smem_u32(sm);
    const int tid = threadIdx.x;
    const int wid = tid >> 5;
    const int lid = tid & 31;
    const int g   = lid >> 2;
    const int tig = lid & 3;
    const int b   = blockIdx.y;
    const int q0  = blockIdx.x * 128;

    // ---- prologue: Q tile (hi/lo) + stage 0, one cp.async group
    #pragma unroll
    for (int u = 0; u < 8; u++) {
        int c = tid + u * 256;            // 0..2047
        int half_ = c >> 10;
        int cc = c & 1023;
        int row = cc >> 3, seg = cc & 7;
        uint32_t dst = sb + half_ * 18432 + row * SRB + seg * 16;
        const __half* src =
            (half_ ? g_Qlo : g_Qhi) + (size_t)(b * SEQ + q0 + row) * DH + seg * 8;
        cp16(dst, src);
    }
    {
        #pragma unroll
        for (int u = 0; u < 4; u++) {
            int c = tid + u * 256;        // 0..1023
            int sel = c >> 9;             // 0 KH, 1 VH
            int cc = c & 511;
            int row = cc >> 3, seg = cc & 7;
            uint32_t dst = sb + AT_STAGE + sel * 9216 + row * SRB + seg * 16;
            const __half* src = sel
                ? g_VThi + ((size_t)b * DH + row) * SEQ + seg * 8
                : g_Khi  + (size_t)(b * SEQ + row) * DH + seg * 8;
            cp16(dst, src);
        }
    }
    CP_COMMIT();

    float acc[8][4];
    #pragma unroll
    for (int j = 0; j < 8; j++)
        #pragma unroll
        for (int i = 0; i < 4; i++) acc[j][i] = 0.0f;
    float l0 = 0.0f, l1 = 0.0f;

    const int mrow = wid * 16;
    const float CEXP = 0.125f * 1.44269504f;
    const int* mr0 = mask + ((size_t)b * SEQ + q0 + mrow + g) * SEQ + 2 * tig;
    const int* mr1 = mr0 + 8 * SEQ;

    // ldmatrix per-lane address components
    const int rowA  = mrow + (lid & 7) + ((lid >> 3) & 1) * 8;
    const int byteA = (lid >> 4) * 16;
    const int rowB  = (lid & 7) + (lid >> 4) * 8;
    const int byteB = ((lid >> 3) & 1) * 16;
    const uint32_t aQH = sb + AT_QH + rowA * SRB + byteA;
    const uint32_t aQL = aQH + 18432;
    const uint32_t aBV = rowB * SRB + byteB;                    // add stage base

    #pragma unroll 1
    for (int kt = 0; kt < SEQ / 64; kt++) {
        if (kt + 1 < SEQ / 64) {
            const int kn = kt + 1;
            const int bsel = kn & 1;
            #pragma unroll
            for (int u = 0; u < 4; u++) {
                int c = tid + u * 256;
                int sel = c >> 9;
                int cc = c & 511;
                int row = cc >> 3, seg = cc & 7;
                uint32_t dst = sb + AT_STAGE + bsel * 18432 + sel * 9216 + row * SRB + seg * 16;
                const __half* src = sel
                    ? g_VThi + ((size_t)b * DH + row) * SEQ + kn * 64 + seg * 8
                    : g_Khi  + (size_t)(b * SEQ + kn * 64 + row) * DH + seg * 8;
                cp16(dst, src);
            }
            CP_COMMIT();
            asm volatile("cp.async.wait_group 1;" ::: "memory");
        } else {
            asm volatile("cp.async.wait_group 0;" ::: "memory");
        }
        __syncthreads();

        const uint32_t stg = sb + AT_STAGE + (kt & 1) * 18432;
        const uint32_t aKH = stg + aBV;
        const uint32_t aVH = aKH + 9216;

        // ---- gemm1: S = (Qhi + Qlo) · Khi
        float s[8][4];
        #pragma unroll
        for (int j = 0; j < 8; j++)
            #pragma unroll
            for (int i = 0; i < 4; i++) s[j][i] = 0.0f;

        #pragma unroll
        for (int ks = 0; ks < 4; ks++) {
            uint32_t ah[4], al[4];
            ldsm4(ah, aQH + ks * 32);
            ldsm4(al, aQL + ks * 32);
            #pragma unroll
            for (int jp = 0; jp < 4; jp++) {
                uint32_t bh[4];
                ldsm4(bh, aKH + jp * (16 * SRB) + ks * 32);
                mma_f16(s[2 * jp],     ah, bh);
                mma_f16(s[2 * jp],     al, bh);
                mma_f16(s[2 * jp + 1], ah, bh + 2);
                mma_f16(s[2 * jp + 1], al, bh + 2);
            }
        }

        // ---- softmax piece: p = mask ? 1 : 2^(s*0.125*log2e); accumulate l
        #pragma unroll
        for (int j = 0; j < 8; j++) {
            int2 m0v = *(const int2*)(mr0 + kt * 64 + j * 8);
            int2 m1v = *(const int2*)(mr1 + kt * 64 + j * 8);
            float p0 = (m0v.x == 1) ? 1.0f : fexp2(s[j][0] * CEXP);
            float p1 = (m0v.y == 1) ? 1.0f : fexp2(s[j][1] * CEXP);
            float p2 = (m1v.x == 1) ? 1.0f : fexp2(s[j][2] * CEXP);
            float p3 = (m1v.y == 1) ? 1.0f : fexp2(s[j][3] * CEXP);
            s[j][0] = p0; s[j][1] = p1; s[j][2] = p2; s[j][3] = p3;
            l0 += p0 + p1;
            l1 += p2 + p3;
        }

        // ---- gemm2: acc += P_fp16 · Vhi
        #pragma unroll
        for (int k2 = 0; k2 < 4; k2++) {
            const float* pa = s[2 * k2];
            const float* pb = s[2 * k2 + 1];
            uint32_t ph[4];
            ph[0] = hpack_hi(pa[0], pa[1]);
            ph[1] = hpack_hi(pa[2], pa[3]);
            ph[2] = hpack_hi(pb[0], pb[1]);
            ph[3] = hpack_hi(pb[2], pb[3]);
            #pragma unroll
            for (int jp = 0; jp < 4; jp++) {
                uint32_t vh[4];
                ldsm4(vh, aVH + jp * (16 * SRB) + k2 * 32);
                mma_f16(acc[2 * jp],     ph, vh);
                mma_f16(acc[2 * jp + 1], ph, vh + 2);
            }
        }
        __syncthreads();
    }

    // ---- epilogue: reduce l across the 4 lanes sharing a row, divide, store
    l0 += __shfl_xor_sync(0xffffffffu, l0, 1);
    l0 += __shfl_xor_sync(0xffffffffu, l0, 2);
    l1 += __shfl_xor_sync(0xffffffffu, l1, 1);
    l1 += __shfl_xor_sync(0xffffffffu, l1, 2);
    float inv0 = 1.0f / l0, inv1 = 1.0f / l1;

    size_t r0 = (size_t)(b * SEQ + q0 + mrow + g) * DH;
    size_t r1 = r0 + 8 * DH;
    #pragma unroll
    for (int j2 = 0; j2 < 8; j2++) {
        int col = j2 * 8 + 2 * tig;
        *(float2*)&out[r0 + col] = make_float2(acc[j2][0] * inv0, acc[j2][1] * inv0);
        *(float2*)&out[r1 + col] = make_float2(acc[j2][2] * inv1, acc[j2][3] * inv1);
    }
}

// ---------------------------------------------------------------------------
extern "C" void kernel_launch(void* const* d_in, const int* in_sizes, int n_in,
                              void* d_out, int out_size)
{
    const float* x    = (const float*)d_in[0];
    const int*   mask = (const int*)d_in[1];
    const float* W    = (const float*)d_in[2];
    const float* bias = (const float*)d_in[3];
    float* out = (float*)d_out;

    (void)in_sizes; (void)n_in; (void)out_size;

    static int attr_set = 0;
    if (!attr_set) {
        cudaFuncSetAttribute(attn_mma_kernel,
                             cudaFuncAttributeMaxDynamicSharedMemorySize, AT_SMEM);
        attr_set = 1;
    }

    wconv_kernel<<<(192 * EMB) / 256, 256>>>(W);
    qkv_mma_kernel<<<NROWS / 64, 256>>>(x, bias);

    dim3 g2(SEQ / 128, BATCH);
    attn_mma_kernel<<<g2, 256, AT_SMEM>>>(mask, out);
}

// round 7
// speedup vs baseline: 2.7283x; 1.1938x over previous
#include <cuda_runtime.h>
#include <cuda_fp16.h>
#include <math.h>
#include <stdint.h>

#define BATCH 8
#define SEQ   2048
#define EMB   1024
#define DH    64
#define NROWS (BATCH * SEQ)   // 16384
#define NKT   (SEQ / 64)      // 32 k-tiles

// Pre-split fp16 operands produced by the QKV kernel.
__device__ __half g_Qhi[NROWS * DH];
__device__ __half g_Qlo[NROWS * DH];
__device__ __half g_Khi[NROWS * DH];
__device__ __half g_VThi[BATCH * DH * SEQ];  // [b][d][s]
__device__ __half g_WhiT[192 * EMB];          // [n][k]

// ---------------------------------------------------------------------------
// helpers
// ---------------------------------------------------------------------------
__device__ __forceinline__ void mma_f16(float* c, const uint32_t* a, const uint32_t* b) {
    asm volatile(
        "mma.sync.aligned.m16n8k16.row.col.f32.f16.f16.f32 "
        "{%0,%1,%2,%3}, {%4,%5,%6,%7}, {%8,%9}, {%0,%1,%2,%3};"
        : "+f"(c[0]), "+f"(c[1]), "+f"(c[2]), "+f"(c[3])
        : "r"(a[0]), "r"(a[1]), "r"(a[2]), "r"(a[3]), "r"(b[0]), "r"(b[1]));
}

__device__ __forceinline__ void ldsm4(uint32_t* r, uint32_t a) {
    asm volatile("ldmatrix.sync.aligned.m8n8.x4.shared.b16 {%0,%1,%2,%3}, [%4];"
        : "=r"(r[0]), "=r"(r[1]), "=r"(r[2]), "=r"(r[3]) : "r"(a));
}

__device__ __forceinline__ uint32_t smem_u32(const void* p) {
    uint32_t a;
    asm("{ .reg .u64 t; cvta.to.shared.u64 t, %1; cvt.u32.u64 %0, t; }"
        : "=r"(a) : "l"(p));
    return a;
}

__device__ __forceinline__ void cp16(uint32_t dst, const void* src) {
    asm volatile("cp.async.cg.shared.global [%0], [%1], 16;" :: "r"(dst), "l"(src));
}
#define CP_COMMIT() asm volatile("cp.async.commit_group;" ::: "memory")

// Fast 2^t on the FMA pipe (abs err ~2.4e-6 for |t| <= ~12).
__device__ __forceinline__ float fexp2(float t) {
    float z = t + 12582912.0f;
    float f = t - (z - 12582912.0f);
    int   e = __float_as_int(z) << 23;
    float p = 0.0013333558f;
    p = fmaf(p, f, 0.0096181291f);
    p = fmaf(p, f, 0.0555041087f);
    p = fmaf(p, f, 0.2402265070f);
    p = fmaf(p, f, 0.6931471806f);
    p = fmaf(p, f, 1.0f);
    return __int_as_float(__float_as_int(p) + e);
}

__device__ __forceinline__ uint32_t hpack_hi(float a, float b) {
    __half2 h = __floats2half2_rn(a, b);
    return *(uint32_t*)&h;
}
__device__ __forceinline__ uint32_t hpack_lo(float a, float b) {
    __half ha = __float2half_rn(a), hb = __float2half_rn(b);
    __half2 l = __halves2half2(__float2half_rn(a - __half2float(ha)),
                               __float2half_rn(b - __half2float(hb)));
    return *(uint32_t*)&l;
}

// ---------------------------------------------------------------------------
// Kernel 0: W [1024,192] fp32 -> transposed hi fp16 [192][1024]
// ---------------------------------------------------------------------------
__global__ void wconv_kernel(const float* __restrict__ W) {
    int idx = blockIdx.x * 256 + threadIdx.x;
    int k = idx & 1023;
    int n = idx >> 10;
    g_WhiT[(size_t)n * EMB + k] = __float2half_rn(W[(size_t)k * 192 + n]);
}

// ---------------------------------------------------------------------------
// Kernel 1: QKV projection (mma.sync, x split hi/lo, W hi only: 2-term).
// Emits split Q (hi/lo), hi K, and transposed VT-hi (via smem staging).
// ---------------------------------------------------------------------------
#define ASTR 40
#define QSM_AHI 0
#define QSM_ALO 5120
#define QSM_BHI 10240
#define QSM_TOT 25600

__global__ __launch_bounds__(256) void qkv_mma_kernel(
    const float* __restrict__ x,
    const float* __restrict__ bias)
{
    __shared__ char qsm[QSM_TOT];
    __half* sAhi = (__half*)(qsm + QSM_AHI);
    __half* sAlo = (__half*)(qsm + QSM_ALO);
    __half* sBhi = (__half*)(qsm + QSM_BHI);

    const int tid = threadIdx.x;
    const int lid = tid & 31;
    const int wid = tid >> 5;
    const int g   = lid >> 2;
    const int tig = lid & 3;
    const int warp_m = wid & 3;
    const int warp_n = wid >> 2;
    const int m0 = blockIdx.x * 64;

    float acc[12][4];
    #pragma unroll
    for (int j = 0; j < 12; j++)
        #pragma unroll
        for (int i = 0; i < 4; i++) acc[j][i] = 0.0f;

    for (int k0 = 0; k0 < EMB; k0 += 32) {
        __syncthreads();
        #pragma unroll
        for (int u = 0; u < 2; u++) {
            int id  = tid + u * 256;
            int row = id >> 3;
            int c4  = id & 7;
            float4 v = *(const float4*)&x[(size_t)(m0 + row) * EMB + k0 + c4 * 4];
            int e = row * ASTR + c4 * 4;
            *(uint32_t*)&sAhi[e]     = hpack_hi(v.x, v.y);
            *(uint32_t*)&sAhi[e + 2] = hpack_hi(v.z, v.w);
            *(uint32_t*)&sAlo[e]     = hpack_lo(v.x, v.y);
            *(uint32_t*)&sAlo[e + 2] = hpack_lo(v.z, v.w);
        }
        #pragma unroll
        for (int u = 0; u < 6; u++) {
            int id  = tid + u * 256;
            int row = id >> 3;
            int c   = id & 7;
            uint2 vh = *(const uint2*)&g_WhiT[(size_t)row * EMB + k0 + c * 4];
            *(uint2*)&sBhi[row * ASTR + c * 4] = vh;
        }
        __syncthreads();

        #pragma unroll
        for (int ks = 0; ks < 2; ks++) {
            const int kb = ks * 16;
            const int ra = warp_m * 16 + g;
            uint32_t ah[4], al[4];
            ah[0] = *(const uint32_t*)&sAhi[ra * ASTR + kb + 2 * tig];
            ah[1] = *(const uint32_t*)&sAhi[(ra + 8) * ASTR + kb + 2 * tig];
            ah[2] = *(const uint32_t*)&sAhi[ra * ASTR + kb + 8 + 2 * tig];
            ah[3] = *(const uint32_t*)&sAhi[(ra + 8) * ASTR + kb + 8 + 2 * tig];
            al[0] = *(const uint32_t*)&sAlo[ra * ASTR + kb + 2 * tig];
            al[1] = *(const uint32_t*)&sAlo[(ra + 8) * ASTR + kb + 2 * tig];
            al[2] = *(const uint32_t*)&sAlo[ra * ASTR + kb + 8 + 2 * tig];
            al[3] = *(const uint32_t*)&sAlo[(ra + 8) * ASTR + kb + 8 + 2 * tig];

            #pragma unroll
            for (int j = 0; j < 12; j++) {
                const int nb = warp_n * 96 + j * 8 + g;
                uint32_t bh[2];
                bh[0] = *(const uint32_t*)&sBhi[nb * ASTR + kb + 2 * tig];
                bh[1] = *(const uint32_t*)&sBhi[nb * ASTR + kb + 8 + 2 * tig];
                mma_f16(acc[j], ah, bh);
                mma_f16(acc[j], al, bh);
            }
        }
    }

    __syncthreads();   // done with A/B tiles; reuse smem for V staging
    float* sV = (float*)qsm;       // [64][68] fp32 = 17408 B
    const int row_l = warp_m * 16 + g;

    #pragma unroll
    for (int j = 0; j < 12; j++) {
        int nglob = warp_n * 96 + j * 8 + 2 * tig;
        float b0 = bias[nglob], b1 = bias[nglob + 1];
        float v0 = acc[j][0] + b0, v1 = acc[j][1] + b1;
        float v2 = acc[j][2] + b0, v3 = acc[j][3] + b1;
        if (nglob < 64) {
            size_t r0 = (size_t)(m0 + row_l) * DH + nglob;
            size_t r1 = (size_t)(m0 + row_l + 8) * DH + nglob;
            *(uint32_t*)&g_Qhi[r0] = hpack_hi(v0, v1);
            *(uint32_t*)&g_Qlo[r0] = hpack_lo(v0, v1);
            *(uint32_t*)&g_Qhi[r1] = hpack_hi(v2, v3);
            *(uint32_t*)&g_Qlo[r1] = hpack_lo(v2, v3);
        } else if (nglob < 128) {
            int col = nglob - 64;
            size_t r0 = (size_t)(m0 + row_l) * DH + col;
            size_t r1 = (size_t)(m0 + row_l + 8) * DH + col;
            *(uint32_t*)&g_Khi[r0] = hpack_hi(v0, v1);
            *(uint32_t*)&g_Khi[r1] = hpack_hi(v2, v3);
        } else {
            int d = nglob - 128;
            sV[row_l * 68 + d]       = v0;
            sV[row_l * 68 + d + 1]   = v1;
            sV[(row_l + 8) * 68 + d]     = v2;
            sV[(row_l + 8) * 68 + d + 1] = v3;
        }
    }
    __syncthreads();

    // Transposed VT store
    {
        int d    = tid >> 2;
        int mseg = (tid & 3) * 16;
        int b    = m0 >> 11;
        int s0   = (m0 & 2047) + mseg;
        uint32_t hw[8];
        #pragma unroll
        for (int i = 0; i < 8; i++) {
            float c0 = sV[(mseg + 2 * i) * 68 + d];
            float c1 = sV[(mseg + 2 * i + 1) * 68 + d];
            hw[i] = hpack_hi(c0, c1);
        }
        size_t base = ((size_t)b * DH + d) * SEQ + s0;
        *(uint4*)&g_VThi[base]     = make_uint4(hw[0], hw[1], hw[2], hw[3]);
        *(uint4*)&g_VThi[base + 8] = make_uint4(hw[4], hw[5], hw[6], hw[7]);
    }
}

// ---------------------------------------------------------------------------
// Kernel 2: fused masked attention, 64-row CTAs (128 thr, 4 warps),
// 4-stage cp.async pipeline, single syncthreads per k-tile, mask prefetch.
// gemm1 = (Qhi+Qlo)·Khi, gemm2 = P_fp16·Vhi.
// ---------------------------------------------------------------------------
#define SRB 144                          // smem row stride bytes (72 halves)
#define AT_QH 0                          // 64 x 144 = 9216
#define AT_QL 9216
#define AT_STAGE 18432                   // 4 stages x (KH 9216 + VH 9216)
#define AT_SMEM (AT_STAGE + 4 * 18432)   // 92160

__global__ __launch_bounds__(128) void attn_mma_kernel(
    const int* __restrict__ mask,
    float* __restrict__ out)
{
    extern __shared__ char sm[];
    const uint32_t sb = smem_u32(sm);
    const int tid = threadIdx.x;
    const int wid = tid >> 5;
    const int lid = tid & 31;
    const int g   = lid >> 2;
    const int tig = lid & 3;
    const int b   = blockIdx.y;
    const int q0  = blockIdx.x * 64;

    // stage issue helper (inlined twice): stage s covers k-tile s
    #define ISSUE_STAGE(s_) do {                                                   \
        int s = (s_);                                                              \
        _Pragma("unroll")                                                          \
        for (int u = 0; u < 8; u++) {                                              \
            int c = tid + u * 128;                                                 \
            int sel = c >> 9;                                                      \
            int cc = c & 511;                                                      \
            int row = cc >> 3, seg = cc & 7;                                       \
            uint32_t dst = sb + AT_STAGE + (s & 3) * 18432 + sel * 9216            \
                         + row * SRB + seg * 16;                                   \
            const __half* src = sel                                                \
                ? g_VThi + ((size_t)b * DH + row) * SEQ + s * 64 + seg * 8         \
                : g_Khi  + (size_t)(b * SEQ + s * 64 + row) * DH + seg * 8;        \
            cp16(dst, src);                                                        \
        }                                                                          \
    } while (0)

    // ---- prologue: Q tile (hi/lo) + stage 0 in group 0; stage 1 in group 1
    #pragma unroll
    for (int u = 0; u < 8; u++) {
        int c = tid + u * 128;            // 0..1023
        int half_ = c >> 9;
        int cc = c & 511;
        int row = cc >> 3, seg = cc & 7;
        uint32_t dst = sb + half_ * 9216 + row * SRB + seg * 16;
        const __half* src =
            (half_ ? g_Qlo : g_Qhi) + (size_t)(b * SEQ + q0 + row) * DH + seg * 8;
        cp16(dst, src);
    }
    ISSUE_STAGE(0);
    CP_COMMIT();
    ISSUE_STAGE(1);
    CP_COMMIT();

    float acc[8][4];
    #pragma unroll
    for (int j = 0; j < 8; j++)
        #pragma unroll
        for (int i = 0; i < 4; i++) acc[j][i] = 0.0f;
    float l0 = 0.0f, l1 = 0.0f;

    const int mrow = wid * 16;
    const float CEXP = 0.125f * 1.44269504f;
    const int* mr0 = mask + ((size_t)b * SEQ + q0 + mrow + g) * SEQ + 2 * tig;
    const int* mr1 = mr0 + 8 * SEQ;

    // ldmatrix per-lane address components
    const int rowA  = mrow + (lid & 7) + ((lid >> 3) & 1) * 8;
    const int byteA = (lid >> 4) * 16;
    const int rowB  = (lid & 7) + (lid >> 4) * 8;
    const int byteB = ((lid >> 3) & 1) * 16;
    const uint32_t aQH = sb + AT_QH + rowA * SRB + byteA;
    const uint32_t aQL = aQH + 9216;
    const uint32_t aBV = rowB * SRB + byteB;     // add stage base

    #pragma unroll 1
    for (int kt = 0; kt < NKT; kt++) {
        // issue depth-2 prefetch, then wait for stage kt, then ONE sync
        if (kt + 2 < NKT) {
            ISSUE_STAGE(kt + 2);
            CP_COMMIT();
            asm volatile("cp.async.wait_group 2;" ::: "memory");
        } else if (kt + 1 < NKT) {
            asm volatile("cp.async.wait_group 1;" ::: "memory");
        } else {
            asm volatile("cp.async.wait_group 0;" ::: "memory");
        }
        __syncthreads();

        // mask prefetch (consumed after gemm1 — latency hidden by MMAs)
        int2 mv0[8], mv1[8];
        #pragma unroll
        for (int j = 0; j < 8; j++) {
            mv0[j] = *(const int2*)(mr0 + kt * 64 + j * 8);
            mv1[j] = *(const int2*)(mr1 + kt * 64 + j * 8);
        }

        const uint32_t stg = sb + AT_STAGE + (kt & 3) * 18432;
        const uint32_t aKH = stg + aBV;
        const uint32_t aVH = aKH + 9216;

        // ---- gemm1: S = (Qhi + Qlo) · Khi
        float s[8][4];
        #pragma unroll
        for (int j = 0; j < 8; j++)
            #pragma unroll
            for (int i = 0; i < 4; i++) s[j][i] = 0.0f;

        #pragma unroll
        for (int ks = 0; ks < 4; ks++) {
            uint32_t ah[4], al[4];
            ldsm4(ah, aQH + ks * 32);
            ldsm4(al, aQL + ks * 32);
            #pragma unroll
            for (int jp = 0; jp < 4; jp++) {
                uint32_t bh[4];
                ldsm4(bh, aKH + jp * (16 * SRB) + ks * 32);
                mma_f16(s[2 * jp],     ah, bh);
                mma_f16(s[2 * jp],     al, bh);
                mma_f16(s[2 * jp + 1], ah, bh + 2);
                mma_f16(s[2 * jp + 1], al, bh + 2);
            }
        }

        // ---- softmax piece: p = mask ? 1 : 2^(s*0.125*log2e); accumulate l
        #pragma unroll
        for (int j = 0; j < 8; j++) {
            float p0 = (mv0[j].x == 1) ? 1.0f : fexp2(s[j][0] * CEXP);
            float p1 = (mv0[j].y == 1) ? 1.0f : fexp2(s[j][1] * CEXP);
            float p2 = (mv1[j].x == 1) ? 1.0f : fexp2(s[j][2] * CEXP);
            float p3 = (mv1[j].y == 1) ? 1.0f : fexp2(s[j][3] * CEXP);
            s[j][0] = p0; s[j][1] = p1; s[j][2] = p2; s[j][3] = p3;
            l0 += p0 + p1;
            l1 += p2 + p3;
        }

        // ---- gemm2: acc += P_fp16 · Vhi
        #pragma unroll
        for (int k2 = 0; k2 < 4; k2++) {
            const float* pa = s[2 * k2];
            const float* pb = s[2 * k2 + 1];
            uint32_t ph[4];
            ph[0] = hpack_hi(pa[0], pa[1]);
            ph[1] = hpack_hi(pa[2], pa[3]);
            ph[2] = hpack_hi(pb[0], pb[1]);
            ph[3] = hpack_hi(pb[2], pb[3]);
            #pragma unroll
            for (int jp = 0; jp < 4; jp++) {
                uint32_t vh[4];
                ldsm4(vh, aVH + jp * (16 * SRB) + k2 * 32);
                mma_f16(acc[2 * jp],     ph, vh);
                mma_f16(acc[2 * jp + 1], ph, vh + 2);
            }
        }
        // no trailing sync: 4-stage ring + top-of-loop sync covers WAR
    }

    // ---- epilogue: reduce l across the 4 lanes sharing a row, divide, store
    l0 += __shfl_xor_sync(0xffffffffu, l0, 1);
    l0 += __shfl_xor_sync(0xffffffffu, l0, 2);
    l1 += __shfl_xor_sync(0xffffffffu, l1, 1);
    l1 += __shfl_xor_sync(0xffffffffu, l1, 2);
    float inv0 = 1.0f / l0, inv1 = 1.0f / l1;

    size_t r0 = (size_t)(b * SEQ + q0 + mrow + g) * DH;
    size_t r1 = r0 + 8 * DH;
    #pragma unroll
    for (int j2 = 0; j2 < 8; j2++) {
        int col = j2 * 8 + 2 * tig;
        *(float2*)&out[r0 + col] = make_float2(acc[j2][0] * inv0, acc[j2][1] * inv0);
        *(float2*)&out[r1 + col] = make_float2(acc[j2][2] * inv1, acc[j2][3] * inv1);
    }
    #undef ISSUE_STAGE
}

// ---------------------------------------------------------------------------
extern "C" void kernel_launch(void* const* d_in, const int* in_sizes, int n_in,
                              void* d_out, int out_size)
{
    const float* x    = (const float*)d_in[0];
    const int*   mask = (const int*)d_in[1];
    const float* W    = (const float*)d_in[2];
    const float* bias = (const float*)d_in[3];
    float* out = (float*)d_out;

    (void)in_sizes; (void)n_in; (void)out_size;

    static int attr_set = 0;
    if (!attr_set) {
        cudaFuncSetAttribute(attn_mma_kernel,
                             cudaFuncAttributeMaxDynamicSharedMemorySize, AT_SMEM);
        attr_set = 1;
    }

    wconv_kernel<<<(192 * EMB) / 256, 256>>>(W);
    qkv_mma_kernel<<<NROWS / 64, 256>>>(x, bias);

    dim3 g2(SEQ / 64, BATCH);
    attn_mma_kernel<<<g2, 128, AT_SMEM>>>(mask, out);
}